// round 13
// baseline (speedup 1.0000x reference)
#include <cuda_runtime.h>
#include <cuda_fp16.h>
#include <cooperative_groups.h>
#include <math.h>
#include <stdint.h>

namespace cg = cooperative_groups;

#define Bb 4
#define Ss 512
#define Dd 512
#define Hh 1024
#define Tt 64
#define Ee 8
#define NSTEPS 4
#define Nn (Bb*Ss)   // 2048 tokens

// ---------------- scratch (static device memory; no allocation) ----------------
__device__ float  g_xt [(size_t)Ee*Nn*Dd];
__device__ __half g_xth[(size_t)Ee*Nn*Dd];
__device__ __half g_h1 [(size_t)Ee*Nn*Hh];
__device__ __half g_h2 [(size_t)Ee*Nn*Hh];
__device__ float g_probs[Nn*Ee];
__device__ float g_lse2[Nn];
__device__ float g_beff[NSTEPS*Ee*Hh];
__device__ __half g_w1[(size_t)Ee*Hh*Dd];
__device__ __half g_w2[(size_t)Ee*Hh*Hh];
__device__ __half g_w3[(size_t)Ee*Dd*Hh];
__device__ float g_s2 [Ee*Hh];
__device__ float g_b2p[Ee*Hh];
__device__ float g_s3 [Ee*Dd];
__device__ float g_b3p[Ee*Dd];
__device__ float2 g_stats[8*(size_t)Ee*Nn];
__device__ int    g_cnt[Ee];
__device__ int    g_tok[Ee*Nn];
__device__ int4   g_asg[Nn];
__device__ float2 g_wts[Nn];

__device__ __forceinline__ uint32_t smem_u32(const void* p) {
    uint32_t a;
    asm("{ .reg .u64 t; cvta.to.shared.u64 t, %1; cvt.u32.u64 %0, t; }" : "=r"(a) : "l"(p));
    return a;
}
__device__ __forceinline__ void ldmx4(uint32_t* r, uint32_t addr) {
    asm volatile("ldmatrix.sync.aligned.m8n8.x4.shared.b16 {%0,%1,%2,%3}, [%4];"
        : "=r"(r[0]), "=r"(r[1]), "=r"(r[2]), "=r"(r[3]) : "r"(addr));
}
__device__ __forceinline__ void mma_f16(float* d, const uint32_t* a, uint32_t b0, uint32_t b1) {
    asm volatile("mma.sync.aligned.m16n8k16.row.col.f32.f16.f16.f32 "
        "{%0,%1,%2,%3}, {%4,%5,%6,%7}, {%8,%9}, {%0,%1,%2,%3};"
        : "+f"(d[0]), "+f"(d[1]), "+f"(d[2]), "+f"(d[3])
        : "r"(a[0]), "r"(a[1]), "r"(a[2]), "r"(a[3]), "r"(b0), "r"(b1));
}
__device__ __forceinline__ void cpasync16(uint32_t dst, const void* src) {
    asm volatile("cp.async.cg.shared.global [%0], [%1], 16;" :: "r"(dst), "l"(src));
}
#define CP_COMMIT() asm volatile("cp.async.commit_group;" ::: "memory")
#define CP_WAIT1()  asm volatile("cp.async.wait_group 1;"  ::: "memory")
#define CP_WAIT0()  asm volatile("cp.async.wait_group 0;"  ::: "memory")

// ---------------- small kernels ----------------
__global__ void zcnt_kernel() {
    if (threadIdx.x < Ee) g_cnt[threadIdx.x] = 0;
}
__global__ void zstats_kernel() {
    size_t idx = (size_t)blockIdx.x*256 + threadIdx.x;
    if (idx < 8*(size_t)Ee*Nn) g_stats[idx] = make_float2(0.f, 0.f);
}

__global__ void router_kernel(const float* __restrict__ x, const float* __restrict__ gw) {
    int n = blockIdx.x;
    __shared__ float xs[Dd];
    __shared__ float lg[Ee];
    int tid = threadIdx.x;
    for (int c = tid; c < Dd; c += 256) xs[c] = x[(size_t)n*Dd + c];
    __syncthreads();
    int w = tid >> 5, lane = tid & 31;
    float s = 0.f;
    const float* wrow = gw + (size_t)w*Dd;
    for (int c = lane; c < Dd; c += 32) s += xs[c]*wrow[c];
    #pragma unroll
    for (int o = 16; o; o >>= 1) s += __shfl_xor_sync(0xffffffffu, s, o);
    if (lane == 0) lg[w] = s;
    __syncthreads();
    if (tid == 0) {
        float m = lg[0];
        #pragma unroll
        for (int e = 1; e < Ee; e++) m = fmaxf(m, lg[e]);
        float ex[Ee], sum = 0.f;
        #pragma unroll
        for (int e = 0; e < Ee; e++) { ex[e] = expf(lg[e]-m); sum += ex[e]; }
        float lse = m + logf(sum);
        g_lse2[n] = lse*lse;
        float p[Ee];
        #pragma unroll
        for (int e = 0; e < Ee; e++) { p[e] = ex[e]/sum; g_probs[n*Ee+e] = p[e]; }
        int i1 = 0;
        #pragma unroll
        for (int e = 1; e < Ee; e++) if (p[e] > p[i1]) i1 = e;
        int i2 = (i1 == 0) ? 1 : 0;
        #pragma unroll
        for (int e = 0; e < Ee; e++) { if (e == i1) continue; if (p[e] > p[i2]) i2 = e; }
        float denom = p[i1] + p[i2] + 1e-9f;
        int s1 = atomicAdd(&g_cnt[i1], 1);
        int s2 = atomicAdd(&g_cnt[i2], 1);
        g_tok[i1*Nn + s1] = n;
        g_tok[i2*Nn + s2] = n;
        g_asg[n] = make_int4(i1, s1, i2, s2);
        g_wts[n] = make_float2(p[i1]/denom, p[i2]/denom);
    }
}

__global__ void gather_kernel(const float* __restrict__ x) {
    size_t flat = (size_t)blockIdx.x*256 + threadIdx.x;
    const size_t perE = (size_t)Nn*Dd/4;
    if (flat >= (size_t)Ee*perE) return;
    int e = (int)(flat / perE);
    size_t rem = flat % perE;
    int slot = (int)(rem / (Dd/4));
    int c4 = (int)(rem % (Dd/4));
    int cnt = g_cnt[e];
    int cntPad = (cnt + 127) & ~127;
    if (slot >= cntPad) return;
    float4 v = make_float4(0.f, 0.f, 0.f, 0.f);
    if (slot < cnt) {
        int tokn = g_tok[e*Nn + slot];
        v = ((const float4*)x)[(size_t)tokn*(Dd/4) + c4];
    }
    size_t o = (size_t)e*Nn*Dd + (size_t)slot*Dd + c4*4;
    *(float4*)(g_xt + o) = v;
    __half2 h0 = __floats2half2_rn(v.x, v.y);
    __half2 h1 = __floats2half2_rn(v.z, v.w);
    *(uint32_t*)(g_xth + o)     = *(uint32_t*)&h0;
    *(uint32_t*)(g_xth + o + 2) = *(uint32_t*)&h1;
}

__global__ void beff_kernel(const float* __restrict__ W1, const float* __restrict__ b1) {
    int row = blockIdx.x*8 + (threadIdx.x >> 5);
    int lane = threadIdx.x & 31;
    if (row >= NSTEPS*Ee*Hh) return;
    int st = row / (Ee*Hh);
    int r  = row % (Ee*Hh);
    float t = st * (1.0f / NSTEPS);
    const float* wrow = W1 + (size_t)r*(Dd+Tt) + Dd;
    const float c0 = -9.210340371976184f / 31.0f;
    float f = __expf(c0 * (float)lane);
    float a = t * f;
    float sn, cs;
    __sincosf(a, &sn, &cs);
    float s = sn*wrow[lane] + cs*wrow[32+lane];
    #pragma unroll
    for (int o = 16; o; o >>= 1) s += __shfl_xor_sync(0xffffffffu, s, o);
    if (lane == 0) g_beff[row] = b1[r] + s;
}

__global__ void wconv_kernel(const float* __restrict__ src, int ld, int cols,
                             __half* __restrict__ dst, long long total) {
    long long idx = (long long)blockIdx.x*256 + threadIdx.x;
    if (idx >= total) return;
    long long r = idx / cols, c = idx % cols;
    dst[idx] = __float2half_rn(src[r*ld + c]);
}

__global__ void wfold_kernel(const float* __restrict__ W, const float* __restrict__ g,
                             const float* __restrict__ be, const float* __restrict__ b,
                             __half* __restrict__ wo, float* __restrict__ So,
                             float* __restrict__ bo, int Ho, int Kc) {
    int row = blockIdx.x*8 + (threadIdx.x >> 5);
    int lane = threadIdx.x & 31;
    if (row >= Ee*Ho) return;
    int e = row / Ho;
    const float* wr = W + (size_t)row*Kc;
    const float* gr = g + (size_t)e*Kc;
    const float* ber = be + (size_t)e*Kc;
    __half* wor = wo + (size_t)row*Kc;
    float s = 0.f, bb = 0.f;
    for (int k = lane; k < Kc; k += 32) {
        float wv = wr[k];
        __half h = __float2half_rn(wv * gr[k]);
        wor[k] = h;
        s  += __half2float(h);
        bb += wv * ber[k];
    }
    #pragma unroll
    for (int o = 16; o; o >>= 1) {
        s  += __shfl_xor_sync(0xffffffffu, s, o);
        bb += __shfl_xor_sync(0xffffffffu, bb, o);
    }
    if (lane == 0) { So[row] = s; bo[row] = b[row] + bb; }
}

// ================= GEMM tile body (shared by standalone + persistent) =================
template<int MODE, int MT>
__device__ __forceinline__ void tile_body(
    const __half* __restrict__ A, const __half* __restrict__ W,
    const float* __restrict__ bias, const float* __restrict__ S,
    const float2* __restrict__ statsIn, float2* __restrict__ statsOut,
    float* __restrict__ Cf, __half* __restrict__ Ch,
    int K, int Ho, float scale, int e, int m0, int n0,
    char* smem, uint32_t sbase)
{
    constexpr int BM   = 32*MT;
    constexpr int ASZA = BM*128;
    constexpr int STG  = ASZA + 16384;
    int tid = threadIdx.x, wid = tid >> 5, lane = tid & 31;
    int wm = wid & 1, wn = wid >> 1;
    A    += (size_t)e*Nn*K;
    W    += (size_t)e*Ho*K;
    bias += (size_t)e*Ho;
    if (MODE != 1) S += (size_t)e*Ho;
    if (MODE == 3) Cf += (size_t)e*Nn*Ho;
    Ch   += (size_t)e*Nn*Ho;
    const float invK = 1.f / (float)K;

    int part = lane >> 3, rip = lane & 7;
    int lrow  = (part & 1)*8 + rip;
    int lcolB = (part >> 1)*16;
    int lxor  = (lrow & 7) << 4;

    float acc[MT][4][4];
    #pragma unroll
    for (int i = 0; i < MT; i++)
        #pragma unroll
        for (int j = 0; j < 4; j++)
            #pragma unroll
            for (int q = 0; q < 4; q++) acc[i][j][q] = 0.f;

    const int nc = K >> 6;

    auto prefetch = [&](int ck) {
        uint32_t st = sbase + (ck & 1)*STG;
        #pragma unroll
        for (int i = 0; i < MT; i++) {
            int flat = tid + 256*i;
            int r = flat >> 3, u = flat & 7;
            uint32_t off = (uint32_t)(r*128 + ((u*16) ^ ((r & 7) << 4)));
            cpasync16(st + off, A + (size_t)(m0 + r)*K + ck*64 + u*8);
        }
        #pragma unroll
        for (int i = 0; i < 4; i++) {
            int flat = tid + 256*i;
            int r = flat >> 3, u = flat & 7;
            uint32_t off = (uint32_t)(r*128 + ((u*16) ^ ((r & 7) << 4)));
            cpasync16(st + ASZA + off, W + (size_t)(n0 + r)*K + ck*64 + u*8);
        }
    };

    prefetch(0);
    CP_COMMIT();

    for (int ck = 0; ck < nc; ck++) {
        if (ck + 1 < nc) { prefetch(ck + 1); CP_COMMIT(); CP_WAIT1(); }
        else             { CP_WAIT0(); }
        __syncthreads();

        uint32_t stb = sbase + (ck & 1)*STG;
        #pragma unroll
        for (int ks = 0; ks < 4; ks++) {
            int colx = (ks*32 + lcolB) ^ lxor;
            uint32_t a[MT][4];
            #pragma unroll
            for (int mi = 0; mi < MT; mi++) {
                uint32_t ad = stb + (wm*(MT*16) + mi*16 + lrow)*128 + colx;
                ldmx4(a[mi], ad);
            }
            uint32_t wv[4][2];
            #pragma unroll
            for (int p = 0; p < 2; p++) {
                uint32_t wd = stb + ASZA + (wn*32 + p*16 + lrow)*128 + colx;
                uint32_t r4[4];
                ldmx4(r4, wd);
                wv[2*p][0] = r4[0]; wv[2*p][1] = r4[2];
                wv[2*p+1][0] = r4[1]; wv[2*p+1][1] = r4[3];
            }
            #pragma unroll
            for (int mi = 0; mi < MT; mi++)
                #pragma unroll
                for (int nt = 0; nt < 4; nt++)
                    mma_f16(acc[mi][nt], a[mi], wv[nt][0], wv[nt][1]);
        }
        __syncthreads();
    }

    // ---- epilogue ----
    int r_l = lane >> 2, c_l = (lane & 3)*2;
    float2 bv[4], sv[4];
    #pragma unroll
    for (int nt = 0; nt < 4; nt++) {
        int col = n0 + wn*32 + nt*8 + c_l;
        bv[nt] = *(const float2*)(bias + col);
        if (MODE != 1) sv[nt] = *(const float2*)(S + col);
    }
    #pragma unroll
    for (int mi = 0; mi < MT; mi++) {
        int row0 = m0 + wm*(MT*16) + mi*16 + r_l;
        float mu0 = 0.f, rs0 = 0.f, mu1 = 0.f, rs1 = 0.f;
        if (MODE != 1) {
            float2 s0 = statsIn[(size_t)e*Nn + row0];
            float2 s1 = statsIn[(size_t)e*Nn + row0 + 8];
            mu0 = s0.x*invK; rs0 = rsqrtf(s0.y*invK - mu0*mu0 + 1e-5f);
            mu1 = s1.x*invK; rs1 = rsqrtf(s1.y*invK - mu1*mu1 + 1e-5f);
        }
        float ls0 = 0.f, lq0 = 0.f, ls1 = 0.f, lq1 = 0.f;
        #pragma unroll
        for (int nt = 0; nt < 4; nt++) {
            int col = n0 + wn*32 + nt*8 + c_l;
            float v0 = acc[mi][nt][0], v1 = acc[mi][nt][1];
            float v2 = acc[mi][nt][2], v3 = acc[mi][nt][3];
            if (MODE == 1) {
                v0 += bv[nt].x; v1 += bv[nt].y; v2 += bv[nt].x; v3 += bv[nt].y;
            } else {
                v0 = rs0*(v0 - mu0*sv[nt].x) + bv[nt].x;
                v1 = rs0*(v1 - mu0*sv[nt].y) + bv[nt].y;
                v2 = rs1*(v2 - mu1*sv[nt].x) + bv[nt].x;
                v3 = rs1*(v3 - mu1*sv[nt].y) + bv[nt].y;
            }
            size_t o0 = (size_t)row0*Ho + col;
            size_t o1 = (size_t)(row0+8)*Ho + col;
            if (MODE != 3) {
                v0 = v0 / (1.f + __expf(-v0));
                v1 = v1 / (1.f + __expf(-v1));
                v2 = v2 / (1.f + __expf(-v2));
                v3 = v3 / (1.f + __expf(-v3));
                __half2 h0 = __floats2half2_rn(v0, v1);
                __half2 h1 = __floats2half2_rn(v2, v3);
                *(uint32_t*)(Ch + o0) = *(uint32_t*)&h0;
                *(uint32_t*)(Ch + o1) = *(uint32_t*)&h1;
                ls0 += v0 + v1; lq0 += v0*v0 + v1*v1;
                ls1 += v2 + v3; lq1 += v2*v2 + v3*v3;
            } else {
                float2 x0 = *(float2*)(Cf + o0), x1 = *(float2*)(Cf + o1);
                float n00 = x0.x + scale*v0, n01 = x0.y + scale*v1;
                float n10 = x1.x + scale*v2, n11 = x1.y + scale*v3;
                *(float2*)(Cf + o0) = make_float2(n00, n01);
                *(float2*)(Cf + o1) = make_float2(n10, n11);
                __half2 h0 = __floats2half2_rn(n00, n01);
                __half2 h1 = __floats2half2_rn(n10, n11);
                *(uint32_t*)(Ch + o0) = *(uint32_t*)&h0;
                *(uint32_t*)(Ch + o1) = *(uint32_t*)&h1;
            }
        }
        if (MODE != 3) {
            ls0 += __shfl_xor_sync(0xffffffffu, ls0, 1); ls0 += __shfl_xor_sync(0xffffffffu, ls0, 2);
            lq0 += __shfl_xor_sync(0xffffffffu, lq0, 1); lq0 += __shfl_xor_sync(0xffffffffu, lq0, 2);
            ls1 += __shfl_xor_sync(0xffffffffu, ls1, 1); ls1 += __shfl_xor_sync(0xffffffffu, ls1, 2);
            lq1 += __shfl_xor_sync(0xffffffffu, lq1, 1); lq1 += __shfl_xor_sync(0xffffffffu, lq1, 2);
            if ((lane & 3) == 0) {
                float* p0 = (float*)&statsOut[(size_t)e*Nn + row0];
                atomicAdd(p0,     ls0);
                atomicAdd(p0 + 1, lq0);
                float* p1 = (float*)&statsOut[(size_t)e*Nn + row0 + 8];
                atomicAdd(p1,     ls1);
                atomicAdd(p1 + 1, lq1);
            }
        }
    }
}

// ---- standalone GEMM (used for step-0 GEMM1 only) ----
template<int MODE, int MT>
__global__ __launch_bounds__(256, 2)
void gemm_hmma(const __half* __restrict__ A, const __half* __restrict__ W,
               const float* __restrict__ bias, const float* __restrict__ S,
               const float2* __restrict__ statsIn, float2* __restrict__ statsOut,
               float* __restrict__ Cf, __half* __restrict__ Ch,
               int K, int Ho, float scale) {
    int e = blockIdx.z;
    const int m0 = blockIdx.y*(32*MT), n0 = blockIdx.x*128;
    if (m0 >= g_cnt[e]) return;
    extern __shared__ __align__(128) char smem[];
    tile_body<MODE, MT>(A, W, bias, S, statsIn, statsOut, Cf, Ch,
                        K, Ho, scale, e, m0, n0, smem, smem_u32(smem));
}

// ---- persistent multi-phase GEMM (cooperative) ----
struct PhaseDesc {
    const __half *A, *W;
    const float *bias, *S;
    const float2 *stIn;
    float2 *stOut;
    float *Cf;
    __half *Ch;
    int K, Ho, mode, mt;
    float scale;
};
struct AllPhases { PhaseDesc p[11]; };

__global__ __launch_bounds__(256, 2)
void gemm_persistent(AllPhases ap, int nPhases) {
    extern __shared__ __align__(128) char smem[];
    uint32_t sbase = smem_u32(smem);
    cg::grid_group grid = cg::this_grid();
    for (int ph = 0; ph < nPhases; ph++) {
        PhaseDesc P = ap.p[ph];
        int bm = 32*P.mt;
        int mtiles = Nn / bm;
        int ntiles = P.Ho / 128;
        int total = mtiles * Ee * ntiles;
        // mi-outer ordering: active tiles (low mi) are front-packed for balance
        for (int t = blockIdx.x; t < total; t += gridDim.x) {
            int mi  = t / (Ee*ntiles);
            int rem = t % (Ee*ntiles);
            int e   = rem / ntiles;
            int ni  = rem % ntiles;
            int m0  = mi*bm;
            if (m0 >= g_cnt[e]) continue;
            if (P.mode == 1)
                tile_body<1,4>(P.A, P.W, P.bias, P.S, P.stIn, P.stOut, P.Cf, P.Ch,
                               P.K, P.Ho, P.scale, e, m0, ni*128, smem, sbase);
            else if (P.mode == 2)
                tile_body<2,4>(P.A, P.W, P.bias, P.S, P.stIn, P.stOut, P.Cf, P.Ch,
                               P.K, P.Ho, P.scale, e, m0, ni*128, smem, sbase);
            else
                tile_body<3,2>(P.A, P.W, P.bias, P.S, P.stIn, P.stOut, P.Cf, P.Ch,
                               P.K, P.Ho, P.scale, e, m0, ni*128, smem, sbase);
        }
        __threadfence();
        grid.sync();
    }
}

// ---------------- combine ----------------
__global__ void combine_kernel(float* __restrict__ out) {
    size_t idx = (size_t)blockIdx.x*256 + threadIdx.x;
    if (idx >= (size_t)Nn*Dd/4) return;
    int n = (int)(idx / (Dd/4));
    int c4 = (int)(idx % (Dd/4));
    int4 a = g_asg[n];
    float2 w = g_wts[n];
    const float4* p1 = (const float4*)(g_xt + ((size_t)a.x*Nn + a.y)*Dd) + c4;
    const float4* p2 = (const float4*)(g_xt + ((size_t)a.z*Nn + a.w)*Dd) + c4;
    float4 v1 = *p1, v2 = *p2;
    float4 r;
    r.x = w.x*v1.x + w.y*v2.x;
    r.y = w.x*v1.y + w.y*v2.y;
    r.z = w.x*v1.z + w.y*v2.z;
    r.w = w.x*v1.w + w.y*v2.w;
    ((float4*)out)[idx] = r;
}

// ---------------- aux losses ----------------
__global__ void aux_kernel(float* __restrict__ out, int out_size) {
    __shared__ float red[256];
    __shared__ float pe[Ee];
    int tid = threadIdx.x;
    float s = 0.f;
    for (int n = tid; n < Nn; n += 256) s += g_lse2[n];
    red[tid] = s; __syncthreads();
    #pragma unroll
    for (int o = 128; o; o >>= 1) { if (tid < o) red[tid] += red[tid+o]; __syncthreads(); }
    float z = red[0] / Nn;
    for (int e = 0; e < Ee; e++) {
        __syncthreads();
        float t = 0.f;
        for (int n = tid; n < Nn; n += 256) t += g_probs[n*Ee+e];
        red[tid] = t; __syncthreads();
        #pragma unroll
        for (int o = 128; o; o >>= 1) { if (tid < o) red[tid] += red[tid+o]; __syncthreads(); }
        if (tid == 0) pe[e] = red[0] / Nn;
    }
    __syncthreads();
    if (tid == 0) {
        float lb = 0.f;
        #pragma unroll
        for (int e = 0; e < Ee; e++) { float d = pe[e] - 1.0f/Ee; lb += d*d; }
        lb *= (float)Ee;
        float aux = 0.001f*z + 0.01f*lb;
        for (long long i = (long long)Nn*Dd; i < out_size; i++) out[i] = aux;
    }
}

// ---------------- host infra ----------------
static cudaStream_t s_prep = nullptr, s_prep2 = nullptr;
static cudaEvent_t s_evFork, s_evW1, s_evW2, s_evW3, s_evB, s_evR, s_evAux;
static int s_grid = 0;
#define SMEM44 (2*(4*32*128 + 16384))   // 65536
static void ensure_infra() {
    if (!s_prep) {
        cudaStreamCreateWithFlags(&s_prep,  cudaStreamNonBlocking);
        cudaStreamCreateWithFlags(&s_prep2, cudaStreamNonBlocking);
        cudaEventCreateWithFlags(&s_evFork, cudaEventDisableTiming);
        cudaEventCreateWithFlags(&s_evW1,   cudaEventDisableTiming);
        cudaEventCreateWithFlags(&s_evW2,   cudaEventDisableTiming);
        cudaEventCreateWithFlags(&s_evW3,   cudaEventDisableTiming);
        cudaEventCreateWithFlags(&s_evB,    cudaEventDisableTiming);
        cudaEventCreateWithFlags(&s_evR,    cudaEventDisableTiming);
        cudaEventCreateWithFlags(&s_evAux,  cudaEventDisableTiming);
        cudaFuncSetAttribute(gemm_hmma<1,4>, cudaFuncAttributeMaxDynamicSharedMemorySize, SMEM44);
        cudaFuncSetAttribute(gemm_persistent, cudaFuncAttributeMaxDynamicSharedMemorySize, SMEM44);
        int numSM = 0;
        cudaDeviceGetAttribute(&numSM, cudaDevAttrMultiProcessorCount, 0);
        int maxB = 0;
        cudaOccupancyMaxActiveBlocksPerMultiprocessor(&maxB, gemm_persistent, 256, SMEM44);
        if (maxB < 1) maxB = 1;
        s_grid = numSM*maxB - 2;           // slack for side-stream aux CTA
        if (s_grid < 32) s_grid = 32;
    }
}

extern "C" void kernel_launch(void* const* d_in, const int* in_sizes, int n_in,
                              void* d_out, int out_size) {
    const float* x   = (const float*)d_in[0];
    const float* gw  = (const float*)d_in[1];
    const float* W1  = (const float*)d_in[2];
    const float* b1  = (const float*)d_in[3];
    const float* g1  = (const float*)d_in[4];
    const float* be1 = (const float*)d_in[5];
    const float* W2  = (const float*)d_in[6];
    const float* b2  = (const float*)d_in[7];
    const float* g2  = (const float*)d_in[8];
    const float* be2 = (const float*)d_in[9];
    const float* W3  = (const float*)d_in[10];
    const float* b3  = (const float*)d_in[11];
    float* out = (float*)d_out;

    float *xt, *beff, *s2p, *b2p, *s3p, *b3p;
    float2* stats;
    __half *xth, *h1, *h2, *w1, *w2, *w3;
    cudaGetSymbolAddress((void**)&xt,    g_xt);
    cudaGetSymbolAddress((void**)&xth,   g_xth);
    cudaGetSymbolAddress((void**)&h1,    g_h1);
    cudaGetSymbolAddress((void**)&h2,    g_h2);
    cudaGetSymbolAddress((void**)&beff,  g_beff);
    cudaGetSymbolAddress((void**)&w1,    g_w1);
    cudaGetSymbolAddress((void**)&w2,    g_w2);
    cudaGetSymbolAddress((void**)&w3,    g_w3);
    cudaGetSymbolAddress((void**)&s2p,   g_s2);
    cudaGetSymbolAddress((void**)&b2p,   g_b2p);
    cudaGetSymbolAddress((void**)&s3p,   g_s3);
    cudaGetSymbolAddress((void**)&b3p,   g_b3p);
    cudaGetSymbolAddress((void**)&stats, g_stats);

    ensure_infra();

    // ---- main stream: routing path ----
    zcnt_kernel<<<1, 32>>>();
    cudaEventRecord(s_evFork, 0);
    cudaStreamWaitEvent(s_prep,  s_evFork, 0);
    cudaStreamWaitEvent(s_prep2, s_evFork, 0);

    // ---- side stream A: stats clear + W1 convert + LN folds ----
    zstats_kernel<<<(int)((8*(size_t)Ee*Nn + 255)/256), 256, 0, s_prep>>>();
    {
        long long t1 = (long long)Ee*Hh*Dd;
        wconv_kernel<<<(int)((t1+255)/256), 256, 0, s_prep>>>(W1, Dd+Tt, Dd, w1, t1);
    }
    cudaEventRecord(s_evW1, s_prep);
    wfold_kernel<<<(Ee*Hh + 7)/8, 256, 0, s_prep>>>(W2, g1, be1, b2, w2, s2p, b2p, Hh, Hh);
    cudaEventRecord(s_evW2, s_prep);
    wfold_kernel<<<(Ee*Dd + 7)/8, 256, 0, s_prep>>>(W3, g2, be2, b3, w3, s3p, b3p, Dd, Hh);
    cudaEventRecord(s_evW3, s_prep);

    // ---- side stream B: effective biases ----
    beff_kernel<<<(NSTEPS*Ee*Hh + 7)/8, 256, 0, s_prep2>>>(W1, b1);
    cudaEventRecord(s_evB, s_prep2);

    // ---- main stream: router + gather ----
    router_kernel<<<Nn, 256>>>(x, gw);
    cudaEventRecord(s_evR, 0);
    gather_kernel<<<(int)(((size_t)Ee*Nn*Dd/4 + 255)/256), 256>>>(x);

    // ---- side stream B: aux loss concurrent with GEMM chain ----
    cudaStreamWaitEvent(s_prep2, s_evR, 0);
    aux_kernel<<<1, 256, 0, s_prep2>>>(out, out_size);
    cudaEventRecord(s_evAux, s_prep2);

    const float dt = 1.0f / NSTEPS;

    // ---- step-0 GEMM1 standalone (needs only w1 + beff + stats) ----
    cudaStreamWaitEvent(0, s_evW1, 0);
    cudaStreamWaitEvent(0, s_evB, 0);
    gemm_hmma<1,4><<<dim3(Hh/128, Nn/128, Ee), 256, SMEM44>>>(
        xth, w1, beff, nullptr, nullptr, stats, nullptr, h1, Dd, Hh, 1.f);

    // ---- persistent cooperative kernel: remaining 11 GEMM phases ----
    cudaStreamWaitEvent(0, s_evW2, 0);
    cudaStreamWaitEvent(0, s_evW3, 0);
    {
        AllPhases ap;
        int np = 0;
        auto add = [&](int mode, int mt, const __half* A, const __half* W,
                       const float* bias, const float* S,
                       const float2* si, float2* so, float* Cf, __half* Ch,
                       int K, int Ho, float sc) {
            ap.p[np++] = PhaseDesc{A, W, bias, S, si, so, Cf, Ch, K, Ho, mode, mt, sc};
        };
        for (int s = 0; s < NSTEPS; s++) {
            float2* st1 = stats + (size_t)(2*s)  *Ee*Nn;
            float2* st2 = stats + (size_t)(2*s+1)*Ee*Nn;
            if (s > 0)
                add(1, 4, xth, w1, beff + s*Ee*Hh, nullptr, nullptr, st1, nullptr, h1, Dd, Hh, 1.f);
            add(2, 4, h1, w2, b2p, s2p, st1, st2, nullptr, h2, Hh, Hh, 1.f);
            add(3, 2, h2, w3, b3p, s3p, st2, nullptr, xt, xth, Hh, Dd, dt);
        }
        cudaLaunchConfig_t cfg = {};
        cfg.gridDim = dim3(s_grid, 1, 1);
        cfg.blockDim = dim3(256, 1, 1);
        cfg.dynamicSmemBytes = SMEM44;
        cfg.stream = 0;
        cudaLaunchAttribute attr[1];
        attr[0].id = cudaLaunchAttributeCooperative;
        attr[0].val.cooperative = 1;
        cfg.attrs = attr;
        cfg.numAttrs = 1;
        cudaLaunchKernelEx(&cfg, gemm_persistent, ap, np);
    }

    combine_kernel<<<(int)(((size_t)Nn*Dd/4 + 255)/256), 256>>>(out);
    cudaStreamWaitEvent(0, s_evAux, 0);
}

// round 14
// speedup vs baseline: 1.0443x; 1.0443x over previous
#include <cuda_runtime.h>
#include <cuda_fp16.h>
#include <math.h>
#include <stdint.h>

#define Bb 4
#define Ss 512
#define Dd 512
#define Hh 1024
#define Tt 64
#define Ee 8
#define NSTEPS 4
#define Nn (Bb*Ss)   // 2048 tokens

// ---------------- scratch (static device memory; no allocation) ----------------
__device__ float  g_xt [(size_t)Ee*Nn*Dd];    // fp32 x_t, compact per expert (slot-major)
__device__ __half g_xth[(size_t)Ee*Nn*Dd];    // x_t fp16, compact
__device__ __half g_h1 [(size_t)Ee*Nn*Hh];    // raw hidden 1 fp16, compact
__device__ __half g_h2 [(size_t)Ee*Nn*Hh];    // raw hidden 2 fp16, compact
__device__ float g_probs[Nn*Ee];
__device__ float g_lse2[Nn];
__device__ float g_beff[NSTEPS*Ee*Hh];        // all steps' effective bias
__device__ __half g_w1[(size_t)Ee*Hh*Dd];     // fp16(W1[:, :, :D])
__device__ __half g_w2[(size_t)Ee*Hh*Hh];     // fp16(g1 ⊙ W2)
__device__ __half g_w3[(size_t)Ee*Dd*Hh];     // fp16(g2 ⊙ W3)
__device__ float g_s2 [Ee*Hh];
__device__ float g_b2p[Ee*Hh];
__device__ float g_s3 [Ee*Dd];
__device__ float g_b3p[Ee*Dd];
__device__ float2 g_stats[8*(size_t)Ee*Nn];
// routing (g_cnt starts zero via static init; combine re-zeros it each launch)
__device__ int    g_cnt[Ee];
__device__ int    g_tok[Ee*Nn];
__device__ int4   g_asg[Nn];
__device__ float2 g_wts[Nn];

__device__ __forceinline__ uint32_t smem_u32(const void* p) {
    uint32_t a;
    asm("{ .reg .u64 t; cvta.to.shared.u64 t, %1; cvt.u32.u64 %0, t; }" : "=r"(a) : "l"(p));
    return a;
}
__device__ __forceinline__ void ldmx4(uint32_t* r, uint32_t addr) {
    asm volatile("ldmatrix.sync.aligned.m8n8.x4.shared.b16 {%0,%1,%2,%3}, [%4];"
        : "=r"(r[0]), "=r"(r[1]), "=r"(r[2]), "=r"(r[3]) : "r"(addr));
}
__device__ __forceinline__ void mma_f16(float* d, const uint32_t* a, uint32_t b0, uint32_t b1) {
    asm volatile("mma.sync.aligned.m16n8k16.row.col.f32.f16.f16.f32 "
        "{%0,%1,%2,%3}, {%4,%5,%6,%7}, {%8,%9}, {%0,%1,%2,%3};"
        : "+f"(d[0]), "+f"(d[1]), "+f"(d[2]), "+f"(d[3])
        : "r"(a[0]), "r"(a[1]), "r"(a[2]), "r"(a[3]), "r"(b0), "r"(b1));
}
__device__ __forceinline__ void cpasync16(uint32_t dst, const void* src) {
    asm volatile("cp.async.cg.shared.global [%0], [%1], 16;" :: "r"(dst), "l"(src));
}
#define CP_COMMIT() asm volatile("cp.async.commit_group;" ::: "memory")
#define CP_WAIT2()  asm volatile("cp.async.wait_group 2;"  ::: "memory")
#define CP_WAIT1()  asm volatile("cp.async.wait_group 1;"  ::: "memory")
#define CP_WAIT0()  asm volatile("cp.async.wait_group 0;"  ::: "memory")

// ---------------- zero stats buffers ----------------
__global__ void zstats_kernel() {
    size_t idx = (size_t)blockIdx.x*256 + threadIdx.x;
    if (idx < 8*(size_t)Ee*Nn) g_stats[idx] = make_float2(0.f, 0.f);
}

// ---------------- router: softmax, top-2, slot assignment ----------------
__global__ void router_kernel(const float* __restrict__ x, const float* __restrict__ gw) {
    int n = blockIdx.x;
    __shared__ float xs[Dd];
    __shared__ float lg[Ee];
    int tid = threadIdx.x;
    for (int c = tid; c < Dd; c += 256) xs[c] = x[(size_t)n*Dd + c];
    __syncthreads();
    int w = tid >> 5, lane = tid & 31;
    float s = 0.f;
    const float* wrow = gw + (size_t)w*Dd;
    for (int c = lane; c < Dd; c += 32) s += xs[c]*wrow[c];
    #pragma unroll
    for (int o = 16; o; o >>= 1) s += __shfl_xor_sync(0xffffffffu, s, o);
    if (lane == 0) lg[w] = s;
    __syncthreads();
    if (tid == 0) {
        float m = lg[0];
        #pragma unroll
        for (int e = 1; e < Ee; e++) m = fmaxf(m, lg[e]);
        float ex[Ee], sum = 0.f;
        #pragma unroll
        for (int e = 0; e < Ee; e++) { ex[e] = expf(lg[e]-m); sum += ex[e]; }
        float lse = m + logf(sum);
        g_lse2[n] = lse*lse;
        float p[Ee];
        #pragma unroll
        for (int e = 0; e < Ee; e++) { p[e] = ex[e]/sum; g_probs[n*Ee+e] = p[e]; }
        int i1 = 0;
        #pragma unroll
        for (int e = 1; e < Ee; e++) if (p[e] > p[i1]) i1 = e;
        int i2 = (i1 == 0) ? 1 : 0;
        #pragma unroll
        for (int e = 0; e < Ee; e++) { if (e == i1) continue; if (p[e] > p[i2]) i2 = e; }
        float denom = p[i1] + p[i2] + 1e-9f;
        int s1 = atomicAdd(&g_cnt[i1], 1);
        int s2 = atomicAdd(&g_cnt[i2], 1);
        g_tok[i1*Nn + s1] = n;
        g_tok[i2*Nn + s2] = n;
        g_asg[n] = make_int4(i1, s1, i2, s2);
        g_wts[n] = make_float2(p[i1]/denom, p[i2]/denom);
    }
}

// ---------------- gather: compact x_t per expert (fp32 + fp16), zero-pad tiles ----------------
__global__ void gather_kernel(const float* __restrict__ x) {
    size_t flat = (size_t)blockIdx.x*256 + threadIdx.x;
    const size_t perE = (size_t)Nn*Dd/4;
    if (flat >= (size_t)Ee*perE) return;
    int e = (int)(flat / perE);
    size_t rem = flat % perE;
    int slot = (int)(rem / (Dd/4));
    int c4 = (int)(rem % (Dd/4));
    int cnt = g_cnt[e];
    int cntPad = (cnt + 127) & ~127;
    if (slot >= cntPad) return;
    float4 v = make_float4(0.f, 0.f, 0.f, 0.f);
    if (slot < cnt) {
        int tokn = g_tok[e*Nn + slot];
        v = ((const float4*)x)[(size_t)tokn*(Dd/4) + c4];
    }
    size_t o = (size_t)e*Nn*Dd + (size_t)slot*Dd + c4*4;
    *(float4*)(g_xt + o) = v;
    __half2 h0 = __floats2half2_rn(v.x, v.y);
    __half2 h1 = __floats2half2_rn(v.z, v.w);
    *(uint32_t*)(g_xth + o)     = *(uint32_t*)&h0;
    *(uint32_t*)(g_xth + o + 2) = *(uint32_t*)&h1;
}

// ---------------- all steps' effective bias: one warp per row ----------------
__global__ void beff_kernel(const float* __restrict__ W1, const float* __restrict__ b1) {
    int row = blockIdx.x*8 + (threadIdx.x >> 5);
    int lane = threadIdx.x & 31;
    if (row >= NSTEPS*Ee*Hh) return;
    int st = row / (Ee*Hh);
    int r  = row % (Ee*Hh);
    float t = st * (1.0f / NSTEPS);
    const float* wrow = W1 + (size_t)r*(Dd+Tt) + Dd;
    const float c0 = -9.210340371976184f / 31.0f;
    float f = __expf(c0 * (float)lane);
    float a = t * f;
    float sn, cs;
    __sincosf(a, &sn, &cs);
    float s = sn*wrow[lane] + cs*wrow[32+lane];
    #pragma unroll
    for (int o = 16; o; o >>= 1) s += __shfl_xor_sync(0xffffffffu, s, o);
    if (lane == 0) g_beff[row] = b1[r] + s;
}

// ---------------- W1 convert: fp32 (strided) -> fp16 ----------------
__global__ void wconv_kernel(const float* __restrict__ src, int ld, int cols,
                             __half* __restrict__ dst, long long total) {
    long long idx = (long long)blockIdx.x*256 + threadIdx.x;
    if (idx >= total) return;
    long long r = idx / cols, c = idx % cols;
    dst[idx] = __float2half_rn(src[r*ld + c]);
}

// ---------------- fold LN affine into weights ----------------
__global__ void wfold_kernel(const float* __restrict__ W, const float* __restrict__ g,
                             const float* __restrict__ be, const float* __restrict__ b,
                             __half* __restrict__ wo, float* __restrict__ So,
                             float* __restrict__ bo, int Ho, int Kc) {
    int row = blockIdx.x*8 + (threadIdx.x >> 5);
    int lane = threadIdx.x & 31;
    if (row >= Ee*Ho) return;
    int e = row / Ho;
    const float* wr = W + (size_t)row*Kc;
    const float* gr = g + (size_t)e*Kc;
    const float* ber = be + (size_t)e*Kc;
    __half* wor = wo + (size_t)row*Kc;
    float s = 0.f, bb = 0.f;
    for (int k = lane; k < Kc; k += 32) {
        float wv = wr[k];
        __half h = __float2half_rn(wv * gr[k]);
        wor[k] = h;
        s  += __half2float(h);
        bb += wv * ber[k];
    }
    #pragma unroll
    for (int o = 16; o; o >>= 1) {
        s  += __shfl_xor_sync(0xffffffffu, s, o);
        bb += __shfl_xor_sync(0xffffffffu, bb, o);
    }
    if (lane == 0) { So[row] = s; bo[row] = b[row] + bb; }
}

// ================= HMMA batched NT GEMM (3-stage cp.async, fused LN-affine + stats) =================
// MODE 1: y = acc + bias; SiLU; emit fp16; stats-out.
// MODE 2: y = rstd*(acc - mu*S) + bias; SiLU; emit fp16; stats-out.
// MODE 3: y = rstd*(acc - mu*S) + bias; xt += scale*y; emit fp32 + fp16.
// MT: M-tiles per CTA (BM = 32*MT). MT=4 for MODE1/2, MT=2 for MODE3 (full wave).
template<int MODE, int MT>
__global__ __launch_bounds__(256, 2)
void gemm_hmma(const __half* __restrict__ A, const __half* __restrict__ W,
               const float* __restrict__ bias, const float* __restrict__ S,
               const float2* __restrict__ statsIn, float2* __restrict__ statsOut,
               float* __restrict__ Cf, __half* __restrict__ Ch,
               int K, int Ho, float scale) {
    constexpr int BM   = 32*MT;
    constexpr int ASZA = BM*128;            // A tile bytes
    constexpr int STG  = ASZA + 16384;      // + W tile (128 rows x 128B)
    int e = blockIdx.z;
    const int m0 = blockIdx.y*BM, n0 = blockIdx.x*128;
    if (m0 >= g_cnt[e]) return;
    extern __shared__ __align__(128) char smem[];
    const uint32_t sbase = smem_u32(smem);
    int tid = threadIdx.x, wid = tid >> 5, lane = tid & 31;
    int wm = wid & 1, wn = wid >> 1;
    A    += (size_t)e*Nn*K;
    W    += (size_t)e*Ho*K;
    bias += (size_t)e*Ho;
    if (MODE != 1) S += (size_t)e*Ho;
    if (MODE == 3) Cf += (size_t)e*Nn*Ho;
    Ch   += (size_t)e*Nn*Ho;
    const float invK = 1.f / (float)K;

    int part = lane >> 3, rip = lane & 7;
    int lrow  = (part & 1)*8 + rip;
    int lcolB = (part >> 1)*16;
    int lxor  = (lrow & 7) << 4;

    float acc[MT][4][4];
    #pragma unroll
    for (int i = 0; i < MT; i++)
        #pragma unroll
        for (int j = 0; j < 4; j++)
            #pragma unroll
            for (int q = 0; q < 4; q++) acc[i][j][q] = 0.f;

    const int nc = K >> 6;

    auto prefetch = [&](int ck) {
        uint32_t st = sbase + (uint32_t)(ck % 3)*STG;
        #pragma unroll
        for (int i = 0; i < MT; i++) {
            int flat = tid + 256*i;
            int r = flat >> 3, u = flat & 7;
            uint32_t off = (uint32_t)(r*128 + ((u*16) ^ ((r & 7) << 4)));
            cpasync16(st + off, A + (size_t)(m0 + r)*K + ck*64 + u*8);
        }
        #pragma unroll
        for (int i = 0; i < 4; i++) {
            int flat = tid + 256*i;
            int r = flat >> 3, u = flat & 7;
            uint32_t off = (uint32_t)(r*128 + ((u*16) ^ ((r & 7) << 4)));
            cpasync16(st + ASZA + off, W + (size_t)(n0 + r)*K + ck*64 + u*8);
        }
    };

    prefetch(0);
    CP_COMMIT();
    if (nc > 1) { prefetch(1); CP_COMMIT(); }

    for (int ck = 0; ck < nc; ck++) {
        if (ck + 2 < nc)      { prefetch(ck + 2); CP_COMMIT(); CP_WAIT2(); }
        else if (ck + 1 < nc) { CP_WAIT1(); }
        else                  { CP_WAIT0(); }
        __syncthreads();

        uint32_t stb = sbase + (uint32_t)(ck % 3)*STG;
        #pragma unroll
        for (int ks = 0; ks < 4; ks++) {
            int colx = (ks*32 + lcolB) ^ lxor;
            uint32_t a[MT][4];
            #pragma unroll
            for (int mi = 0; mi < MT; mi++) {
                uint32_t ad = stb + (wm*(MT*16) + mi*16 + lrow)*128 + colx;
                ldmx4(a[mi], ad);
            }
            uint32_t wv[4][2];
            #pragma unroll
            for (int p = 0; p < 2; p++) {
                uint32_t wd = stb + ASZA + (wn*32 + p*16 + lrow)*128 + colx;
                uint32_t r4[4];
                ldmx4(r4, wd);
                wv[2*p][0] = r4[0]; wv[2*p][1] = r4[2];
                wv[2*p+1][0] = r4[1]; wv[2*p+1][1] = r4[3];
            }
            #pragma unroll
            for (int mi = 0; mi < MT; mi++)
                #pragma unroll
                for (int nt = 0; nt < 4; nt++)
                    mma_f16(acc[mi][nt], a[mi], wv[nt][0], wv[nt][1]);
        }
        __syncthreads();
    }

    // ---- epilogue ----
    int r_l = lane >> 2, c_l = (lane & 3)*2;
    float2 bv[4], sv[4];
    #pragma unroll
    for (int nt = 0; nt < 4; nt++) {
        int col = n0 + wn*32 + nt*8 + c_l;
        bv[nt] = *(const float2*)(bias + col);
        if (MODE != 1) sv[nt] = *(const float2*)(S + col);
    }
    #pragma unroll
    for (int mi = 0; mi < MT; mi++) {
        int row0 = m0 + wm*(MT*16) + mi*16 + r_l;
        float mu0 = 0.f, rs0 = 0.f, mu1 = 0.f, rs1 = 0.f;
        if (MODE != 1) {
            float2 s0 = statsIn[(size_t)e*Nn + row0];
            float2 s1 = statsIn[(size_t)e*Nn + row0 + 8];
            mu0 = s0.x*invK; rs0 = rsqrtf(s0.y*invK - mu0*mu0 + 1e-5f);
            mu1 = s1.x*invK; rs1 = rsqrtf(s1.y*invK - mu1*mu1 + 1e-5f);
        }
        float ls0 = 0.f, lq0 = 0.f, ls1 = 0.f, lq1 = 0.f;
        #pragma unroll
        for (int nt = 0; nt < 4; nt++) {
            int col = n0 + wn*32 + nt*8 + c_l;
            float v0 = acc[mi][nt][0], v1 = acc[mi][nt][1];
            float v2 = acc[mi][nt][2], v3 = acc[mi][nt][3];
            if (MODE == 1) {
                v0 += bv[nt].x; v1 += bv[nt].y; v2 += bv[nt].x; v3 += bv[nt].y;
            } else {
                v0 = rs0*(v0 - mu0*sv[nt].x) + bv[nt].x;
                v1 = rs0*(v1 - mu0*sv[nt].y) + bv[nt].y;
                v2 = rs1*(v2 - mu1*sv[nt].x) + bv[nt].x;
                v3 = rs1*(v3 - mu1*sv[nt].y) + bv[nt].y;
            }
            size_t o0 = (size_t)row0*Ho + col;
            size_t o1 = (size_t)(row0+8)*Ho + col;
            if (MODE != 3) {
                v0 = v0 / (1.f + __expf(-v0));
                v1 = v1 / (1.f + __expf(-v1));
                v2 = v2 / (1.f + __expf(-v2));
                v3 = v3 / (1.f + __expf(-v3));
                __half2 h0 = __floats2half2_rn(v0, v1);
                __half2 h1 = __floats2half2_rn(v2, v3);
                *(uint32_t*)(Ch + o0) = *(uint32_t*)&h0;
                *(uint32_t*)(Ch + o1) = *(uint32_t*)&h1;
                ls0 += v0 + v1; lq0 += v0*v0 + v1*v1;
                ls1 += v2 + v3; lq1 += v2*v2 + v3*v3;
            } else {
                float2 x0 = *(float2*)(Cf + o0), x1 = *(float2*)(Cf + o1);
                float n00 = x0.x + scale*v0, n01 = x0.y + scale*v1;
                float n10 = x1.x + scale*v2, n11 = x1.y + scale*v3;
                *(float2*)(Cf + o0) = make_float2(n00, n01);
                *(float2*)(Cf + o1) = make_float2(n10, n11);
                __half2 h0 = __floats2half2_rn(n00, n01);
                __half2 h1 = __floats2half2_rn(n10, n11);
                *(uint32_t*)(Ch + o0) = *(uint32_t*)&h0;
                *(uint32_t*)(Ch + o1) = *(uint32_t*)&h1;
            }
        }
        if (MODE != 3) {
            ls0 += __shfl_xor_sync(0xffffffffu, ls0, 1); ls0 += __shfl_xor_sync(0xffffffffu, ls0, 2);
            lq0 += __shfl_xor_sync(0xffffffffu, lq0, 1); lq0 += __shfl_xor_sync(0xffffffffu, lq0, 2);
            ls1 += __shfl_xor_sync(0xffffffffu, ls1, 1); ls1 += __shfl_xor_sync(0xffffffffu, ls1, 2);
            lq1 += __shfl_xor_sync(0xffffffffu, lq1, 1); lq1 += __shfl_xor_sync(0xffffffffu, lq1, 2);
            if ((lane & 3) == 0) {
                float* p0 = (float*)&statsOut[(size_t)e*Nn + row0];
                atomicAdd(p0,     ls0);
                atomicAdd(p0 + 1, lq0);
                float* p1 = (float*)&statsOut[(size_t)e*Nn + row0 + 8];
                atomicAdd(p1,     ls1);
                atomicAdd(p1 + 1, lq1);
            }
        }
    }
}

// ---------------- combine: gather 2 expert rows per token; re-zero g_cnt ----------------
__global__ void combine_kernel(float* __restrict__ out) {
    if (blockIdx.x == 0 && threadIdx.x < Ee) g_cnt[threadIdx.x] = 0;  // invariant for next launch
    size_t idx = (size_t)blockIdx.x*256 + threadIdx.x;
    if (idx >= (size_t)Nn*Dd/4) return;
    int n = (int)(idx / (Dd/4));
    int c4 = (int)(idx % (Dd/4));
    int4 a = g_asg[n];
    float2 w = g_wts[n];
    const float4* p1 = (const float4*)(g_xt + ((size_t)a.x*Nn + a.y)*Dd) + c4;
    const float4* p2 = (const float4*)(g_xt + ((size_t)a.z*Nn + a.w)*Dd) + c4;
    float4 v1 = *p1, v2 = *p2;
    float4 r;
    r.x = w.x*v1.x + w.y*v2.x;
    r.y = w.x*v1.y + w.y*v2.y;
    r.z = w.x*v1.z + w.y*v2.z;
    r.w = w.x*v1.w + w.y*v2.w;
    ((float4*)out)[idx] = r;
}

// ---------------- aux losses (independent of GEMM chain) ----------------
__global__ void aux_kernel(float* __restrict__ out, int out_size) {
    __shared__ float red[256];
    __shared__ float pe[Ee];
    int tid = threadIdx.x;
    float s = 0.f;
    for (int n = tid; n < Nn; n += 256) s += g_lse2[n];
    red[tid] = s; __syncthreads();
    #pragma unroll
    for (int o = 128; o; o >>= 1) { if (tid < o) red[tid] += red[tid+o]; __syncthreads(); }
    float z = red[0] / Nn;
    for (int e = 0; e < Ee; e++) {
        __syncthreads();
        float t = 0.f;
        for (int n = tid; n < Nn; n += 256) t += g_probs[n*Ee+e];
        red[tid] = t; __syncthreads();
        #pragma unroll
        for (int o = 128; o; o >>= 1) { if (tid < o) red[tid] += red[tid+o]; __syncthreads(); }
        if (tid == 0) pe[e] = red[0] / Nn;
    }
    __syncthreads();
    if (tid == 0) {
        float lb = 0.f;
        #pragma unroll
        for (int e = 0; e < Ee; e++) { float d = pe[e] - 1.0f/Ee; lb += d*d; }
        lb *= (float)Ee;
        float aux = 0.001f*z + 0.01f*lb;
        for (long long i = (long long)Nn*Dd; i < out_size; i++) out[i] = aux;
    }
}

// ---------------- side streams / events (host-side infra, created once) ----------------
static cudaStream_t s_prep = nullptr, s_prep2 = nullptr;
static cudaEvent_t s_evFork, s_evW1, s_evW2, s_evW3, s_evB, s_evR, s_evAux;
static void ensure_infra() {
    if (!s_prep) {
        cudaStreamCreateWithFlags(&s_prep,  cudaStreamNonBlocking);
        cudaStreamCreateWithFlags(&s_prep2, cudaStreamNonBlocking);
        cudaEventCreateWithFlags(&s_evFork, cudaEventDisableTiming);
        cudaEventCreateWithFlags(&s_evW1,   cudaEventDisableTiming);
        cudaEventCreateWithFlags(&s_evW2,   cudaEventDisableTiming);
        cudaEventCreateWithFlags(&s_evW3,   cudaEventDisableTiming);
        cudaEventCreateWithFlags(&s_evB,    cudaEventDisableTiming);
        cudaEventCreateWithFlags(&s_evR,    cudaEventDisableTiming);
        cudaEventCreateWithFlags(&s_evAux,  cudaEventDisableTiming);
    }
}

extern "C" void kernel_launch(void* const* d_in, const int* in_sizes, int n_in,
                              void* d_out, int out_size) {
    const float* x   = (const float*)d_in[0];
    const float* gw  = (const float*)d_in[1];
    const float* W1  = (const float*)d_in[2];
    const float* b1  = (const float*)d_in[3];
    const float* g1  = (const float*)d_in[4];
    const float* be1 = (const float*)d_in[5];
    const float* W2  = (const float*)d_in[6];
    const float* b2  = (const float*)d_in[7];
    const float* g2  = (const float*)d_in[8];
    const float* be2 = (const float*)d_in[9];
    const float* W3  = (const float*)d_in[10];
    const float* b3  = (const float*)d_in[11];
    float* out = (float*)d_out;

    float *xt, *beff, *s2p, *b2p, *s3p, *b3p;
    float2* stats;
    __half *xth, *h1, *h2, *w1, *w2, *w3;
    cudaGetSymbolAddress((void**)&xt,    g_xt);
    cudaGetSymbolAddress((void**)&xth,   g_xth);
    cudaGetSymbolAddress((void**)&h1,    g_h1);
    cudaGetSymbolAddress((void**)&h2,    g_h2);
    cudaGetSymbolAddress((void**)&beff,  g_beff);
    cudaGetSymbolAddress((void**)&w1,    g_w1);
    cudaGetSymbolAddress((void**)&w2,    g_w2);
    cudaGetSymbolAddress((void**)&w3,    g_w3);
    cudaGetSymbolAddress((void**)&s2p,   g_s2);
    cudaGetSymbolAddress((void**)&b2p,   g_b2p);
    cudaGetSymbolAddress((void**)&s3p,   g_s3);
    cudaGetSymbolAddress((void**)&b3p,   g_b3p);
    cudaGetSymbolAddress((void**)&stats, g_stats);

    ensure_infra();

    const int SMEM44 = 3*(4*32*128 + 16384);   // MT=4, 3 stages: 98304
    const int SMEM32 = 3*(2*32*128 + 16384);   // MT=2, 3 stages: 73728
    cudaFuncSetAttribute(gemm_hmma<1,4>, cudaFuncAttributeMaxDynamicSharedMemorySize, SMEM44);
    cudaFuncSetAttribute(gemm_hmma<2,4>, cudaFuncAttributeMaxDynamicSharedMemorySize, SMEM44);
    cudaFuncSetAttribute(gemm_hmma<3,2>, cudaFuncAttributeMaxDynamicSharedMemorySize, SMEM32);

    // ---- fork side streams ----
    cudaEventRecord(s_evFork, 0);
    cudaStreamWaitEvent(s_prep,  s_evFork, 0);
    cudaStreamWaitEvent(s_prep2, s_evFork, 0);

    // ---- side stream A: stats clear + W1 convert + LN folds ----
    zstats_kernel<<<(int)((8*(size_t)Ee*Nn + 255)/256), 256, 0, s_prep>>>();
    {
        long long t1 = (long long)Ee*Hh*Dd;
        wconv_kernel<<<(int)((t1+255)/256), 256, 0, s_prep>>>(W1, Dd+Tt, Dd, w1, t1);
    }
    cudaEventRecord(s_evW1, s_prep);
    wfold_kernel<<<(Ee*Hh + 7)/8, 256, 0, s_prep>>>(W2, g1, be1, b2, w2, s2p, b2p, Hh, Hh);
    cudaEventRecord(s_evW2, s_prep);
    wfold_kernel<<<(Ee*Dd + 7)/8, 256, 0, s_prep>>>(W3, g2, be2, b3, w3, s3p, b3p, Dd, Hh);
    cudaEventRecord(s_evW3, s_prep);

    // ---- side stream B: effective biases (warp-parallel) ----
    beff_kernel<<<(NSTEPS*Ee*Hh + 7)/8, 256, 0, s_prep2>>>(W1, b1);
    cudaEventRecord(s_evB, s_prep2);

    // ---- main stream: router + gather (g_cnt zeroed by previous launch's combine) ----
    router_kernel<<<Nn, 256>>>(x, gw);
    cudaEventRecord(s_evR, 0);
    gather_kernel<<<(int)(((size_t)Ee*Nn*Dd/4 + 255)/256), 256>>>(x);

    // ---- side stream B: aux loss runs concurrently with the GEMM chain ----
    cudaStreamWaitEvent(s_prep2, s_evR, 0);
    aux_kernel<<<1, 256, 0, s_prep2>>>(out, out_size);
    cudaEventRecord(s_evAux, s_prep2);

    // ---- main stream: flow-matching GEMM chain ----
    const float dt = 1.0f / NSTEPS;
    for (int s = 0; s < NSTEPS; s++) {
        float2* st1 = stats + (size_t)(2*s)  *Ee*Nn;
        float2* st2 = stats + (size_t)(2*s+1)*Ee*Nn;
        if (s == 0) { cudaStreamWaitEvent(0, s_evW1, 0); cudaStreamWaitEvent(0, s_evB, 0); }
        gemm_hmma<1,4><<<dim3(Hh/128, Nn/128, Ee), 256, SMEM44>>>(
            xth, w1, beff + s*Ee*Hh, nullptr, nullptr, st1, nullptr, h1, Dd, Hh, 1.f);
        if (s == 0) cudaStreamWaitEvent(0, s_evW2, 0);
        gemm_hmma<2,4><<<dim3(Hh/128, Nn/128, Ee), 256, SMEM44>>>(
            h1, w2, b2p, s2p, st1, st2, nullptr, h2, Hh, Hh, 1.f);
        if (s == 0) cudaStreamWaitEvent(0, s_evW3, 0);
        gemm_hmma<3,2><<<dim3(Dd/128, Nn/64, Ee), 256, SMEM32>>>(
            h2, w3, b3p, s3p, st2, nullptr, xt, xth, Hh, Dd, dt);
    }

    combine_kernel<<<(int)(((size_t)Nn*Dd/4 + 255)/256), 256>>>(out);
    cudaStreamWaitEvent(0, s_evAux, 0);   // join side stream before capture ends
}

// round 15
// speedup vs baseline: 1.0731x; 1.0276x over previous
#include <cuda_runtime.h>
#include <cuda_fp16.h>
#include <math.h>
#include <stdint.h>

#define Bb 4
#define Ss 512
#define Dd 512
#define Hh 1024
#define Tt 64
#define Ee 8
#define NSTEPS 4
#define Nn (Bb*Ss)   // 2048 tokens

// ---------------- scratch (static device memory; no allocation) ----------------
__device__ float  g_xt [(size_t)Ee*Nn*Dd];    // fp32 x_t, compact per expert (slot-major)
__device__ __half g_xth[(size_t)Ee*Nn*Dd];    // x_t fp16, compact
__device__ __half g_h1 [(size_t)Ee*Nn*Hh];
__device__ __half g_h2 [(size_t)Ee*Nn*Hh];
__device__ float g_probs[Nn*Ee];
__device__ float g_lse2[Nn];
__device__ float g_beff[NSTEPS*Ee*Hh];
__device__ __half g_w1[(size_t)Ee*Hh*Dd];
__device__ __half g_w2[(size_t)Ee*Hh*Hh];
__device__ __half g_w3[(size_t)Ee*Dd*Hh];
__device__ float g_s2 [Ee*Hh];
__device__ float g_b2p[Ee*Hh];
__device__ float g_s3 [Ee*Dd];
__device__ float g_b3p[Ee*Dd];
__device__ float2 g_stats[8*(size_t)Ee*Nn];
// routing (g_cnt starts zero via static init; combine re-zeros it each launch)
__device__ int    g_cnt[Ee];
__device__ int4   g_asg[Nn];
__device__ float2 g_wts[Nn];

__device__ __forceinline__ uint32_t smem_u32(const void* p) {
    uint32_t a;
    asm("{ .reg .u64 t; cvta.to.shared.u64 t, %1; cvt.u32.u64 %0, t; }" : "=r"(a) : "l"(p));
    return a;
}
__device__ __forceinline__ void ldmx4(uint32_t* r, uint32_t addr) {
    asm volatile("ldmatrix.sync.aligned.m8n8.x4.shared.b16 {%0,%1,%2,%3}, [%4];"
        : "=r"(r[0]), "=r"(r[1]), "=r"(r[2]), "=r"(r[3]) : "r"(addr));
}
__device__ __forceinline__ void mma_f16(float* d, const uint32_t* a, uint32_t b0, uint32_t b1) {
    asm volatile("mma.sync.aligned.m16n8k16.row.col.f32.f16.f16.f32 "
        "{%0,%1,%2,%3}, {%4,%5,%6,%7}, {%8,%9}, {%0,%1,%2,%3};"
        : "+f"(d[0]), "+f"(d[1]), "+f"(d[2]), "+f"(d[3])
        : "r"(a[0]), "r"(a[1]), "r"(a[2]), "r"(a[3]), "r"(b0), "r"(b1));
}
__device__ __forceinline__ void cpasync16(uint32_t dst, const void* src) {
    asm volatile("cp.async.cg.shared.global [%0], [%1], 16;" :: "r"(dst), "l"(src));
}
#define CP_COMMIT() asm volatile("cp.async.commit_group;" ::: "memory")
#define CP_WAIT1()  asm volatile("cp.async.wait_group 1;"  ::: "memory")
#define CP_WAIT0()  asm volatile("cp.async.wait_group 0;"  ::: "memory")

// ---------------- zero stats buffers ----------------
__global__ void zstats_kernel() {
    size_t idx = (size_t)blockIdx.x*256 + threadIdx.x;
    if (idx < 8*(size_t)Ee*Nn) g_stats[idx] = make_float2(0.f, 0.f);
}

// ---------------- router + fused gather ----------------
// Computes softmax/top-2, claims slots, and writes the compact fp32+fp16 x_t
// copies for both selected experts directly from SMEM. Pad rows (>= cnt) of
// partial tiles are left unwritten: every downstream op is row-independent,
// and combine never reads rows >= cnt, so garbage there is harmless.
__global__ void router_kernel(const float* __restrict__ x, const float* __restrict__ gw) {
    int n = blockIdx.x;
    __shared__ float xs[Dd];
    __shared__ float lg[Ee];
    __shared__ int   sdst[2];   // e1*Nn+s1, e2*Nn+s2
    int tid = threadIdx.x;
    for (int c = tid; c < Dd; c += 256) xs[c] = x[(size_t)n*Dd + c];
    __syncthreads();
    int w = tid >> 5, lane = tid & 31;
    float s = 0.f;
    const float* wrow = gw + (size_t)w*Dd;
    for (int c = lane; c < Dd; c += 32) s += xs[c]*wrow[c];
    #pragma unroll
    for (int o = 16; o; o >>= 1) s += __shfl_xor_sync(0xffffffffu, s, o);
    if (lane == 0) lg[w] = s;
    __syncthreads();
    if (tid == 0) {
        float m = lg[0];
        #pragma unroll
        for (int e = 1; e < Ee; e++) m = fmaxf(m, lg[e]);
        float ex[Ee], sum = 0.f;
        #pragma unroll
        for (int e = 0; e < Ee; e++) { ex[e] = expf(lg[e]-m); sum += ex[e]; }
        float lse = m + logf(sum);
        g_lse2[n] = lse*lse;
        float p[Ee];
        #pragma unroll
        for (int e = 0; e < Ee; e++) { p[e] = ex[e]/sum; g_probs[n*Ee+e] = p[e]; }
        int i1 = 0;
        #pragma unroll
        for (int e = 1; e < Ee; e++) if (p[e] > p[i1]) i1 = e;
        int i2 = (i1 == 0) ? 1 : 0;
        #pragma unroll
        for (int e = 0; e < Ee; e++) { if (e == i1) continue; if (p[e] > p[i2]) i2 = e; }
        float denom = p[i1] + p[i2] + 1e-9f;
        int s1 = atomicAdd(&g_cnt[i1], 1);
        int s2 = atomicAdd(&g_cnt[i2], 1);
        g_asg[n] = make_int4(i1, s1, i2, s2);
        g_wts[n] = make_float2(p[i1]/denom, p[i2]/denom);
        sdst[0] = i1*Nn + s1;
        sdst[1] = i2*Nn + s2;
    }
    __syncthreads();
    // fused gather: write both compact copies (fp32 + fp16), coalesced per row
    #pragma unroll
    for (int cpy = 0; cpy < 2; cpy++) {
        size_t base = (size_t)sdst[cpy]*Dd;
        for (int c4 = tid; c4 < Dd/4; c4 += 256) {
            float4 v = *(const float4*)&xs[c4*4];
            *(float4*)(g_xt + base + c4*4) = v;
            __half2 h0 = __floats2half2_rn(v.x, v.y);
            __half2 h1 = __floats2half2_rn(v.z, v.w);
            *(uint32_t*)(g_xth + base + c4*4)     = *(uint32_t*)&h0;
            *(uint32_t*)(g_xth + base + c4*4 + 2) = *(uint32_t*)&h1;
        }
    }
}

// ---------------- all steps' effective bias: one warp per row ----------------
__global__ void beff_kernel(const float* __restrict__ W1, const float* __restrict__ b1) {
    int row = blockIdx.x*8 + (threadIdx.x >> 5);
    int lane = threadIdx.x & 31;
    if (row >= NSTEPS*Ee*Hh) return;
    int st = row / (Ee*Hh);
    int r  = row % (Ee*Hh);
    float t = st * (1.0f / NSTEPS);
    const float* wrow = W1 + (size_t)r*(Dd+Tt) + Dd;
    const float c0 = -9.210340371976184f / 31.0f;
    float f = __expf(c0 * (float)lane);
    float a = t * f;
    float sn, cs;
    __sincosf(a, &sn, &cs);
    float s = sn*wrow[lane] + cs*wrow[32+lane];
    #pragma unroll
    for (int o = 16; o; o >>= 1) s += __shfl_xor_sync(0xffffffffu, s, o);
    if (lane == 0) g_beff[row] = b1[r] + s;
}

// ---------------- W1 convert: fp32 (strided) -> fp16 ----------------
__global__ void wconv_kernel(const float* __restrict__ src, int ld, int cols,
                             __half* __restrict__ dst, long long total) {
    long long idx = (long long)blockIdx.x*256 + threadIdx.x;
    if (idx >= total) return;
    long long r = idx / cols, c = idx % cols;
    dst[idx] = __float2half_rn(src[r*ld + c]);
}

// ---------------- fold LN affine into weights ----------------
__global__ void wfold_kernel(const float* __restrict__ W, const float* __restrict__ g,
                             const float* __restrict__ be, const float* __restrict__ b,
                             __half* __restrict__ wo, float* __restrict__ So,
                             float* __restrict__ bo, int Ho, int Kc) {
    int row = blockIdx.x*8 + (threadIdx.x >> 5);
    int lane = threadIdx.x & 31;
    if (row >= Ee*Ho) return;
    int e = row / Ho;
    const float* wr = W + (size_t)row*Kc;
    const float* gr = g + (size_t)e*Kc;
    const float* ber = be + (size_t)e*Kc;
    __half* wor = wo + (size_t)row*Kc;
    float s = 0.f, bb = 0.f;
    for (int k = lane; k < Kc; k += 32) {
        float wv = wr[k];
        __half h = __float2half_rn(wv * gr[k]);
        wor[k] = h;
        s  += __half2float(h);
        bb += wv * ber[k];
    }
    #pragma unroll
    for (int o = 16; o; o >>= 1) {
        s  += __shfl_xor_sync(0xffffffffu, s, o);
        bb += __shfl_xor_sync(0xffffffffu, bb, o);
    }
    if (lane == 0) { So[row] = s; bo[row] = b[row] + bb; }
}

// ================= HMMA batched NT GEMM (2-stage cp.async, fused LN-affine + stats) =================
// MODE 1: y = acc + bias; SiLU; emit fp16; stats-out.
// MODE 2: y = rstd*(acc - mu*S) + bias; SiLU; emit fp16; stats-out.
// MODE 3: y = rstd*(acc - mu*S) + bias; xt += scale*y; emit fp32 + fp16.
// MT: M-tiles per CTA (BM = 32*MT). MT=4 for MODE1/2, MT=2 for MODE3 (full wave).
template<int MODE, int MT>
__global__ __launch_bounds__(256, 2)
void gemm_hmma(const __half* __restrict__ A, const __half* __restrict__ W,
               const float* __restrict__ bias, const float* __restrict__ S,
               const float2* __restrict__ statsIn, float2* __restrict__ statsOut,
               float* __restrict__ Cf, __half* __restrict__ Ch,
               int K, int Ho, float scale) {
    constexpr int BM   = 32*MT;
    constexpr int ASZA = BM*128;            // A tile bytes
    constexpr int STG  = ASZA + 16384;      // + W tile (128 rows x 128B)
    int e = blockIdx.z;
    const int m0 = blockIdx.y*BM, n0 = blockIdx.x*128;
    if (m0 >= g_cnt[e]) return;
    extern __shared__ __align__(128) char smem[];
    const uint32_t sbase = smem_u32(smem);
    int tid = threadIdx.x, wid = tid >> 5, lane = tid & 31;
    int wm = wid & 1, wn = wid >> 1;
    A    += (size_t)e*Nn*K;
    W    += (size_t)e*Ho*K;
    bias += (size_t)e*Ho;
    if (MODE != 1) S += (size_t)e*Ho;
    if (MODE == 3) Cf += (size_t)e*Nn*Ho;
    Ch   += (size_t)e*Nn*Ho;
    const float invK = 1.f / (float)K;

    int part = lane >> 3, rip = lane & 7;
    int lrow  = (part & 1)*8 + rip;
    int lcolB = (part >> 1)*16;
    int lxor  = (lrow & 7) << 4;

    float acc[MT][4][4];
    #pragma unroll
    for (int i = 0; i < MT; i++)
        #pragma unroll
        for (int j = 0; j < 4; j++)
            #pragma unroll
            for (int q = 0; q < 4; q++) acc[i][j][q] = 0.f;

    const int nc = K >> 6;

    auto prefetch = [&](int ck) {
        uint32_t st = sbase + (ck & 1)*STG;
        #pragma unroll
        for (int i = 0; i < MT; i++) {
            int flat = tid + 256*i;
            int r = flat >> 3, u = flat & 7;
            uint32_t off = (uint32_t)(r*128 + ((u*16) ^ ((r & 7) << 4)));
            cpasync16(st + off, A + (size_t)(m0 + r)*K + ck*64 + u*8);
        }
        #pragma unroll
        for (int i = 0; i < 4; i++) {
            int flat = tid + 256*i;
            int r = flat >> 3, u = flat & 7;
            uint32_t off = (uint32_t)(r*128 + ((u*16) ^ ((r & 7) << 4)));
            cpasync16(st + ASZA + off, W + (size_t)(n0 + r)*K + ck*64 + u*8);
        }
    };

    prefetch(0);
    CP_COMMIT();

    for (int ck = 0; ck < nc; ck++) {
        if (ck + 1 < nc) { prefetch(ck + 1); CP_COMMIT(); CP_WAIT1(); }
        else             { CP_WAIT0(); }
        __syncthreads();

        uint32_t stb = sbase + (ck & 1)*STG;
        #pragma unroll
        for (int ks = 0; ks < 4; ks++) {
            int colx = (ks*32 + lcolB) ^ lxor;
            uint32_t a[MT][4];
            #pragma unroll
            for (int mi = 0; mi < MT; mi++) {
                uint32_t ad = stb + (wm*(MT*16) + mi*16 + lrow)*128 + colx;
                ldmx4(a[mi], ad);
            }
            uint32_t wv[4][2];
            #pragma unroll
            for (int p = 0; p < 2; p++) {
                uint32_t wd = stb + ASZA + (wn*32 + p*16 + lrow)*128 + colx;
                uint32_t r4[4];
                ldmx4(r4, wd);
                wv[2*p][0] = r4[0]; wv[2*p][1] = r4[2];
                wv[2*p+1][0] = r4[1]; wv[2*p+1][1] = r4[3];
            }
            #pragma unroll
            for (int mi = 0; mi < MT; mi++)
                #pragma unroll
                for (int nt = 0; nt < 4; nt++)
                    mma_f16(acc[mi][nt], a[mi], wv[nt][0], wv[nt][1]);
        }
        __syncthreads();
    }

    // ---- epilogue ----
    int r_l = lane >> 2, c_l = (lane & 3)*2;
    float2 bv[4], sv[4];
    #pragma unroll
    for (int nt = 0; nt < 4; nt++) {
        int col = n0 + wn*32 + nt*8 + c_l;
        bv[nt] = *(const float2*)(bias + col);
        if (MODE != 1) sv[nt] = *(const float2*)(S + col);
    }
    #pragma unroll
    for (int mi = 0; mi < MT; mi++) {
        int row0 = m0 + wm*(MT*16) + mi*16 + r_l;
        float mu0 = 0.f, rs0 = 0.f, mu1 = 0.f, rs1 = 0.f;
        if (MODE != 1) {
            float2 s0 = statsIn[(size_t)e*Nn + row0];
            float2 s1 = statsIn[(size_t)e*Nn + row0 + 8];
            mu0 = s0.x*invK; rs0 = rsqrtf(s0.y*invK - mu0*mu0 + 1e-5f);
            mu1 = s1.x*invK; rs1 = rsqrtf(s1.y*invK - mu1*mu1 + 1e-5f);
        }
        float ls0 = 0.f, lq0 = 0.f, ls1 = 0.f, lq1 = 0.f;
        #pragma unroll
        for (int nt = 0; nt < 4; nt++) {
            int col = n0 + wn*32 + nt*8 + c_l;
            float v0 = acc[mi][nt][0], v1 = acc[mi][nt][1];
            float v2 = acc[mi][nt][2], v3 = acc[mi][nt][3];
            if (MODE == 1) {
                v0 += bv[nt].x; v1 += bv[nt].y; v2 += bv[nt].x; v3 += bv[nt].y;
            } else {
                v0 = rs0*(v0 - mu0*sv[nt].x) + bv[nt].x;
                v1 = rs0*(v1 - mu0*sv[nt].y) + bv[nt].y;
                v2 = rs1*(v2 - mu1*sv[nt].x) + bv[nt].x;
                v3 = rs1*(v3 - mu1*sv[nt].y) + bv[nt].y;
            }
            size_t o0 = (size_t)row0*Ho + col;
            size_t o1 = (size_t)(row0+8)*Ho + col;
            if (MODE != 3) {
                v0 = v0 / (1.f + __expf(-v0));
                v1 = v1 / (1.f + __expf(-v1));
                v2 = v2 / (1.f + __expf(-v2));
                v3 = v3 / (1.f + __expf(-v3));
                __half2 h0 = __floats2half2_rn(v0, v1);
                __half2 h1 = __floats2half2_rn(v2, v3);
                *(uint32_t*)(Ch + o0) = *(uint32_t*)&h0;
                *(uint32_t*)(Ch + o1) = *(uint32_t*)&h1;
                ls0 += v0 + v1; lq0 += v0*v0 + v1*v1;
                ls1 += v2 + v3; lq1 += v2*v2 + v3*v3;
            } else {
                float2 x0 = *(float2*)(Cf + o0), x1 = *(float2*)(Cf + o1);
                float n00 = x0.x + scale*v0, n01 = x0.y + scale*v1;
                float n10 = x1.x + scale*v2, n11 = x1.y + scale*v3;
                *(float2*)(Cf + o0) = make_float2(n00, n01);
                *(float2*)(Cf + o1) = make_float2(n10, n11);
                __half2 h0 = __floats2half2_rn(n00, n01);
                __half2 h1 = __floats2half2_rn(n10, n11);
                *(uint32_t*)(Ch + o0) = *(uint32_t*)&h0;
                *(uint32_t*)(Ch + o1) = *(uint32_t*)&h1;
            }
        }
        if (MODE != 3) {
            ls0 += __shfl_xor_sync(0xffffffffu, ls0, 1); ls0 += __shfl_xor_sync(0xffffffffu, ls0, 2);
            lq0 += __shfl_xor_sync(0xffffffffu, lq0, 1); lq0 += __shfl_xor_sync(0xffffffffu, lq0, 2);
            ls1 += __shfl_xor_sync(0xffffffffu, ls1, 1); ls1 += __shfl_xor_sync(0xffffffffu, ls1, 2);
            lq1 += __shfl_xor_sync(0xffffffffu, lq1, 1); lq1 += __shfl_xor_sync(0xffffffffu, lq1, 2);
            if ((lane & 3) == 0) {
                float* p0 = (float*)&statsOut[(size_t)e*Nn + row0];
                atomicAdd(p0,     ls0);
                atomicAdd(p0 + 1, lq0);
                float* p1 = (float*)&statsOut[(size_t)e*Nn + row0 + 8];
                atomicAdd(p1,     ls1);
                atomicAdd(p1 + 1, lq1);
            }
        }
    }
}

// ---------------- combine: gather 2 expert rows per token; re-zero g_cnt ----------------
__global__ void combine_kernel(float* __restrict__ out) {
    if (blockIdx.x == 0 && threadIdx.x < Ee) g_cnt[threadIdx.x] = 0;  // invariant for next launch
    size_t idx = (size_t)blockIdx.x*256 + threadIdx.x;
    if (idx >= (size_t)Nn*Dd/4) return;
    int n = (int)(idx / (Dd/4));
    int c4 = (int)(idx % (Dd/4));
    int4 a = g_asg[n];
    float2 w = g_wts[n];
    const float4* p1 = (const float4*)(g_xt + ((size_t)a.x*Nn + a.y)*Dd) + c4;
    const float4* p2 = (const float4*)(g_xt + ((size_t)a.z*Nn + a.w)*Dd) + c4;
    float4 v1 = *p1, v2 = *p2;
    float4 r;
    r.x = w.x*v1.x + w.y*v2.x;
    r.y = w.x*v1.y + w.y*v2.y;
    r.z = w.x*v1.z + w.y*v2.z;
    r.w = w.x*v1.w + w.y*v2.w;
    ((float4*)out)[idx] = r;
}

// ---------------- aux losses (independent of GEMM chain) ----------------
__global__ void aux_kernel(float* __restrict__ out, int out_size) {
    __shared__ float red[256];
    __shared__ float pe[Ee];
    int tid = threadIdx.x;
    float s = 0.f;
    for (int n = tid; n < Nn; n += 256) s += g_lse2[n];
    red[tid] = s; __syncthreads();
    #pragma unroll
    for (int o = 128; o; o >>= 1) { if (tid < o) red[tid] += red[tid+o]; __syncthreads(); }
    float z = red[0] / Nn;
    for (int e = 0; e < Ee; e++) {
        __syncthreads();
        float t = 0.f;
        for (int n = tid; n < Nn; n += 256) t += g_probs[n*Ee+e];
        red[tid] = t; __syncthreads();
        #pragma unroll
        for (int o = 128; o; o >>= 1) { if (tid < o) red[tid] += red[tid+o]; __syncthreads(); }
        if (tid == 0) pe[e] = red[0] / Nn;
    }
    __syncthreads();
    if (tid == 0) {
        float lb = 0.f;
        #pragma unroll
        for (int e = 0; e < Ee; e++) { float d = pe[e] - 1.0f/Ee; lb += d*d; }
        lb *= (float)Ee;
        float aux = 0.001f*z + 0.01f*lb;
        for (long long i = (long long)Nn*Dd; i < out_size; i++) out[i] = aux;
    }
}

// ---------------- side streams / events (host-side infra, created once) ----------------
static cudaStream_t s_prep = nullptr, s_prep2 = nullptr;
static cudaEvent_t s_evFork, s_evW1, s_evW2, s_evW3, s_evB, s_evR, s_evAux;
static void ensure_infra() {
    if (!s_prep) {
        cudaStreamCreateWithFlags(&s_prep,  cudaStreamNonBlocking);
        cudaStreamCreateWithFlags(&s_prep2, cudaStreamNonBlocking);
        cudaEventCreateWithFlags(&s_evFork, cudaEventDisableTiming);
        cudaEventCreateWithFlags(&s_evW1,   cudaEventDisableTiming);
        cudaEventCreateWithFlags(&s_evW2,   cudaEventDisableTiming);
        cudaEventCreateWithFlags(&s_evW3,   cudaEventDisableTiming);
        cudaEventCreateWithFlags(&s_evB,    cudaEventDisableTiming);
        cudaEventCreateWithFlags(&s_evR,    cudaEventDisableTiming);
        cudaEventCreateWithFlags(&s_evAux,  cudaEventDisableTiming);
    }
}

extern "C" void kernel_launch(void* const* d_in, const int* in_sizes, int n_in,
                              void* d_out, int out_size) {
    const float* x   = (const float*)d_in[0];
    const float* gw  = (const float*)d_in[1];
    const float* W1  = (const float*)d_in[2];
    const float* b1  = (const float*)d_in[3];
    const float* g1  = (const float*)d_in[4];
    const float* be1 = (const float*)d_in[5];
    const float* W2  = (const float*)d_in[6];
    const float* b2  = (const float*)d_in[7];
    const float* g2  = (const float*)d_in[8];
    const float* be2 = (const float*)d_in[9];
    const float* W3  = (const float*)d_in[10];
    const float* b3  = (const float*)d_in[11];
    float* out = (float*)d_out;

    float *xt, *beff, *s2p, *b2p, *s3p, *b3p;
    float2* stats;
    __half *xth, *h1, *h2, *w1, *w2, *w3;
    cudaGetSymbolAddress((void**)&xt,    g_xt);
    cudaGetSymbolAddress((void**)&xth,   g_xth);
    cudaGetSymbolAddress((void**)&h1,    g_h1);
    cudaGetSymbolAddress((void**)&h2,    g_h2);
    cudaGetSymbolAddress((void**)&beff,  g_beff);
    cudaGetSymbolAddress((void**)&w1,    g_w1);
    cudaGetSymbolAddress((void**)&w2,    g_w2);
    cudaGetSymbolAddress((void**)&w3,    g_w3);
    cudaGetSymbolAddress((void**)&s2p,   g_s2);
    cudaGetSymbolAddress((void**)&b2p,   g_b2p);
    cudaGetSymbolAddress((void**)&s3p,   g_s3);
    cudaGetSymbolAddress((void**)&b3p,   g_b3p);
    cudaGetSymbolAddress((void**)&stats, g_stats);

    ensure_infra();

    const int SMEM44 = 2*(4*32*128 + 16384);   // MT=4: 65536
    const int SMEM32 = 2*(2*32*128 + 16384);   // MT=2: 49152
    cudaFuncSetAttribute(gemm_hmma<1,4>, cudaFuncAttributeMaxDynamicSharedMemorySize, SMEM44);
    cudaFuncSetAttribute(gemm_hmma<2,4>, cudaFuncAttributeMaxDynamicSharedMemorySize, SMEM44);
    cudaFuncSetAttribute(gemm_hmma<3,2>, cudaFuncAttributeMaxDynamicSharedMemorySize, SMEM32);

    // ---- fork side streams ----
    cudaEventRecord(s_evFork, 0);
    cudaStreamWaitEvent(s_prep,  s_evFork, 0);
    cudaStreamWaitEvent(s_prep2, s_evFork, 0);

    // ---- side stream A: stats clear + W1 convert + LN folds ----
    zstats_kernel<<<(int)((8*(size_t)Ee*Nn + 255)/256), 256, 0, s_prep>>>();
    {
        long long t1 = (long long)Ee*Hh*Dd;
        wconv_kernel<<<(int)((t1+255)/256), 256, 0, s_prep>>>(W1, Dd+Tt, Dd, w1, t1);
    }
    cudaEventRecord(s_evW1, s_prep);
    wfold_kernel<<<(Ee*Hh + 7)/8, 256, 0, s_prep>>>(W2, g1, be1, b2, w2, s2p, b2p, Hh, Hh);
    cudaEventRecord(s_evW2, s_prep);
    wfold_kernel<<<(Ee*Dd + 7)/8, 256, 0, s_prep>>>(W3, g2, be2, b3, w3, s3p, b3p, Dd, Hh);
    cudaEventRecord(s_evW3, s_prep);

    // ---- side stream B: effective biases (warp-parallel) ----
    beff_kernel<<<(NSTEPS*Ee*Hh + 7)/8, 256, 0, s_prep2>>>(W1, b1);
    cudaEventRecord(s_evB, s_prep2);

    // ---- main stream: fused router+gather (g_cnt zeroed by previous combine) ----
    router_kernel<<<Nn, 256>>>(x, gw);
    cudaEventRecord(s_evR, 0);

    // ---- side stream B: aux loss runs concurrently with the GEMM chain ----
    cudaStreamWaitEvent(s_prep2, s_evR, 0);
    aux_kernel<<<1, 256, 0, s_prep2>>>(out, out_size);
    cudaEventRecord(s_evAux, s_prep2);

    // ---- main stream: flow-matching GEMM chain ----
    const float dt = 1.0f / NSTEPS;
    for (int s = 0; s < NSTEPS; s++) {
        float2* st1 = stats + (size_t)(2*s)  *Ee*Nn;
        float2* st2 = stats + (size_t)(2*s+1)*Ee*Nn;
        if (s == 0) { cudaStreamWaitEvent(0, s_evW1, 0); cudaStreamWaitEvent(0, s_evB, 0); }
        gemm_hmma<1,4><<<dim3(Hh/128, Nn/128, Ee), 256, SMEM44>>>(
            xth, w1, beff + s*Ee*Hh, nullptr, nullptr, st1, nullptr, h1, Dd, Hh, 1.f);
        if (s == 0) cudaStreamWaitEvent(0, s_evW2, 0);
        gemm_hmma<2,4><<<dim3(Hh/128, Nn/128, Ee), 256, SMEM44>>>(
            h1, w2, b2p, s2p, st1, st2, nullptr, h2, Hh, Hh, 1.f);
        if (s == 0) cudaStreamWaitEvent(0, s_evW3, 0);
        gemm_hmma<3,2><<<dim3(Dd/128, Nn/64, Ee), 256, SMEM32>>>(
            h2, w3, b3p, s3p, st2, nullptr, xt, xth, Hh, Dd, dt);
    }

    combine_kernel<<<(int)(((size_t)Nn*Dd/4 + 255)/256), 256>>>(out);
    cudaStreamWaitEvent(0, s_evAux, 0);   // join side stream before capture ends
}

// round 16
// speedup vs baseline: 1.0913x; 1.0169x over previous
#include <cuda_runtime.h>
#include <cuda_fp16.h>
#include <math.h>
#include <stdint.h>

#define Bb 4
#define Ss 512
#define Dd 512
#define Hh 1024
#define Tt 64
#define Ee 8
#define NSTEPS 4
#define Nn (Bb*Ss)   // 2048 tokens

// ---------------- scratch (static device memory; no allocation) ----------------
__device__ float  g_xt [(size_t)Ee*Nn*Dd];    // fp32 x_t, compact per expert (slot-major)
__device__ __half g_xth[(size_t)Ee*Nn*Dd];    // x_t fp16, compact
__device__ __half g_h1 [(size_t)Ee*Nn*Hh];
__device__ __half g_h2 [(size_t)Ee*Nn*Hh];
__device__ float g_probs[Nn*Ee];
__device__ float g_lse2[Nn];
__device__ float g_beff[NSTEPS*Ee*Hh];
__device__ __half g_w1[(size_t)Ee*Hh*Dd];
__device__ __half g_w2[(size_t)Ee*Hh*Hh];
__device__ __half g_w3[(size_t)Ee*Dd*Hh];
__device__ float g_s2 [Ee*Hh];
__device__ float g_b2p[Ee*Hh];
__device__ float g_s3 [Ee*Dd];
__device__ float g_b3p[Ee*Dd];
__device__ float2 g_stats[8*(size_t)Ee*Nn];
// routing (g_cnt starts zero via static init; combine re-zeros it each launch)
__device__ int    g_cnt[Ee];
__device__ int4   g_asg[Nn];
__device__ float2 g_wts[Nn];

__device__ __forceinline__ uint32_t smem_u32(const void* p) {
    uint32_t a;
    asm("{ .reg .u64 t; cvta.to.shared.u64 t, %1; cvt.u32.u64 %0, t; }" : "=r"(a) : "l"(p));
    return a;
}
__device__ __forceinline__ void ldmx4(uint32_t* r, uint32_t addr) {
    asm volatile("ldmatrix.sync.aligned.m8n8.x4.shared.b16 {%0,%1,%2,%3}, [%4];"
        : "=r"(r[0]), "=r"(r[1]), "=r"(r[2]), "=r"(r[3]) : "r"(addr));
}
__device__ __forceinline__ void mma_f16(float* d, const uint32_t* a, uint32_t b0, uint32_t b1) {
    asm volatile("mma.sync.aligned.m16n8k16.row.col.f32.f16.f16.f32 "
        "{%0,%1,%2,%3}, {%4,%5,%6,%7}, {%8,%9}, {%0,%1,%2,%3};"
        : "+f"(d[0]), "+f"(d[1]), "+f"(d[2]), "+f"(d[3])
        : "r"(a[0]), "r"(a[1]), "r"(a[2]), "r"(a[3]), "r"(b0), "r"(b1));
}
__device__ __forceinline__ void cpasync16(uint32_t dst, const void* src) {
    asm volatile("cp.async.cg.shared.global [%0], [%1], 16;" :: "r"(dst), "l"(src));
}
#define CP_COMMIT() asm volatile("cp.async.commit_group;" ::: "memory")
#define CP_WAIT1()  asm volatile("cp.async.wait_group 1;"  ::: "memory")
#define CP_WAIT0()  asm volatile("cp.async.wait_group 0;"  ::: "memory")

// ---------------- zero stats buffers ----------------
__global__ void zstats_kernel() {
    size_t idx = (size_t)blockIdx.x*256 + threadIdx.x;
    if (idx < 8*(size_t)Ee*Nn) g_stats[idx] = make_float2(0.f, 0.f);
}

// ---------------- router + fused gather ----------------
__global__ void router_kernel(const float* __restrict__ x, const float* __restrict__ gw) {
    int n = blockIdx.x;
    __shared__ float xs[Dd];
    __shared__ float lg[Ee];
    __shared__ int   sdst[2];
    int tid = threadIdx.x;
    for (int c = tid; c < Dd; c += 256) xs[c] = x[(size_t)n*Dd + c];
    __syncthreads();
    int w = tid >> 5, lane = tid & 31;
    float s = 0.f;
    const float* wrow = gw + (size_t)w*Dd;
    for (int c = lane; c < Dd; c += 32) s += xs[c]*wrow[c];
    #pragma unroll
    for (int o = 16; o; o >>= 1) s += __shfl_xor_sync(0xffffffffu, s, o);
    if (lane == 0) lg[w] = s;
    __syncthreads();
    if (tid == 0) {
        float m = lg[0];
        #pragma unroll
        for (int e = 1; e < Ee; e++) m = fmaxf(m, lg[e]);
        float ex[Ee], sum = 0.f;
        #pragma unroll
        for (int e = 0; e < Ee; e++) { ex[e] = expf(lg[e]-m); sum += ex[e]; }
        float lse = m + logf(sum);
        g_lse2[n] = lse*lse;
        float p[Ee];
        #pragma unroll
        for (int e = 0; e < Ee; e++) { p[e] = ex[e]/sum; g_probs[n*Ee+e] = p[e]; }
        int i1 = 0;
        #pragma unroll
        for (int e = 1; e < Ee; e++) if (p[e] > p[i1]) i1 = e;
        int i2 = (i1 == 0) ? 1 : 0;
        #pragma unroll
        for (int e = 0; e < Ee; e++) { if (e == i1) continue; if (p[e] > p[i2]) i2 = e; }
        float denom = p[i1] + p[i2] + 1e-9f;
        int s1 = atomicAdd(&g_cnt[i1], 1);
        int s2 = atomicAdd(&g_cnt[i2], 1);
        g_asg[n] = make_int4(i1, s1, i2, s2);
        g_wts[n] = make_float2(p[i1]/denom, p[i2]/denom);
        sdst[0] = i1*Nn + s1;
        sdst[1] = i2*Nn + s2;
    }
    __syncthreads();
    #pragma unroll
    for (int cpy = 0; cpy < 2; cpy++) {
        size_t base = (size_t)sdst[cpy]*Dd;
        for (int c4 = tid; c4 < Dd/4; c4 += 256) {
            float4 v = *(const float4*)&xs[c4*4];
            *(float4*)(g_xt + base + c4*4) = v;
            __half2 h0 = __floats2half2_rn(v.x, v.y);
            __half2 h1 = __floats2half2_rn(v.z, v.w);
            *(uint32_t*)(g_xth + base + c4*4)     = *(uint32_t*)&h0;
            *(uint32_t*)(g_xth + base + c4*4 + 2) = *(uint32_t*)&h1;
        }
    }
}

// ---------------- all steps' effective bias: one warp per row ----------------
__global__ void beff_kernel(const float* __restrict__ W1, const float* __restrict__ b1) {
    int row = blockIdx.x*8 + (threadIdx.x >> 5);
    int lane = threadIdx.x & 31;
    if (row >= NSTEPS*Ee*Hh) return;
    int st = row / (Ee*Hh);
    int r  = row % (Ee*Hh);
    float t = st * (1.0f / NSTEPS);
    const float* wrow = W1 + (size_t)r*(Dd+Tt) + Dd;
    const float c0 = -9.210340371976184f / 31.0f;
    float f = __expf(c0 * (float)lane);
    float a = t * f;
    float sn, cs;
    __sincosf(a, &sn, &cs);
    float s = sn*wrow[lane] + cs*wrow[32+lane];
    #pragma unroll
    for (int o = 16; o; o >>= 1) s += __shfl_xor_sync(0xffffffffu, s, o);
    if (lane == 0) g_beff[row] = b1[r] + s;
}

// ---------------- W1 convert: fp32 (strided) -> fp16 ----------------
__global__ void wconv_kernel(const float* __restrict__ src, int ld, int cols,
                             __half* __restrict__ dst, long long total) {
    long long idx = (long long)blockIdx.x*256 + threadIdx.x;
    if (idx >= total) return;
    long long r = idx / cols, c = idx % cols;
    dst[idx] = __float2half_rn(src[r*ld + c]);
}

// ---------------- fold LN affine into weights ----------------
__global__ void wfold_kernel(const float* __restrict__ W, const float* __restrict__ g,
                             const float* __restrict__ be, const float* __restrict__ b,
                             __half* __restrict__ wo, float* __restrict__ So,
                             float* __restrict__ bo, int Ho, int Kc) {
    int row = blockIdx.x*8 + (threadIdx.x >> 5);
    int lane = threadIdx.x & 31;
    if (row >= Ee*Ho) return;
    int e = row / Ho;
    const float* wr = W + (size_t)row*Kc;
    const float* gr = g + (size_t)e*Kc;
    const float* ber = be + (size_t)e*Kc;
    __half* wor = wo + (size_t)row*Kc;
    float s = 0.f, bb = 0.f;
    for (int k = lane; k < Kc; k += 32) {
        float wv = wr[k];
        __half h = __float2half_rn(wv * gr[k]);
        wor[k] = h;
        s  += __half2float(h);
        bb += wv * ber[k];
    }
    #pragma unroll
    for (int o = 16; o; o >>= 1) {
        s  += __shfl_xor_sync(0xffffffffu, s, o);
        bb += __shfl_xor_sync(0xffffffffu, bb, o);
    }
    if (lane == 0) { So[row] = s; bo[row] = b[row] + bb; }
}

// ================= HMMA batched NT GEMM (2-stage cp.async, fused LN-affine + stats) =================
// Grid: (ntiles, Ee, mtiles) — mi is slowest-varying so active tiles (low mi)
// are front-packed in launch order: wave 1 is fully productive.
// MODE 1: y = acc + bias; SiLU; emit fp16; stats-out.
// MODE 2: y = rstd*(acc - mu*S) + bias; SiLU; emit fp16; stats-out.
// MODE 3: y = rstd*(acc - mu*S) + bias; xt += scale*y; emit fp32 + fp16.
template<int MODE, int MT>
__global__ __launch_bounds__(256, 2)
void gemm_hmma(const __half* __restrict__ A, const __half* __restrict__ W,
               const float* __restrict__ bias, const float* __restrict__ S,
               const float2* __restrict__ statsIn, float2* __restrict__ statsOut,
               float* __restrict__ Cf, __half* __restrict__ Ch,
               int K, int Ho, float scale) {
    constexpr int BM   = 32*MT;
    constexpr int ASZA = BM*128;
    constexpr int STG  = ASZA + 16384;
    int e = blockIdx.y;
    const int m0 = blockIdx.z*BM, n0 = blockIdx.x*128;
    if (m0 >= g_cnt[e]) return;
    extern __shared__ __align__(128) char smem[];
    const uint32_t sbase = smem_u32(smem);
    int tid = threadIdx.x, wid = tid >> 5, lane = tid & 31;
    int wm = wid & 1, wn = wid >> 1;
    A    += (size_t)e*Nn*K;
    W    += (size_t)e*Ho*K;
    bias += (size_t)e*Ho;
    if (MODE != 1) S += (size_t)e*Ho;
    if (MODE == 3) Cf += (size_t)e*Nn*Ho;
    Ch   += (size_t)e*Nn*Ho;
    const float invK = 1.f / (float)K;

    int part = lane >> 3, rip = lane & 7;
    int lrow  = (part & 1)*8 + rip;
    int lcolB = (part >> 1)*16;
    int lxor  = (lrow & 7) << 4;

    float acc[MT][4][4];
    #pragma unroll
    for (int i = 0; i < MT; i++)
        #pragma unroll
        for (int j = 0; j < 4; j++)
            #pragma unroll
            for (int q = 0; q < 4; q++) acc[i][j][q] = 0.f;

    const int nc = K >> 6;

    auto prefetch = [&](int ck) {
        uint32_t st = sbase + (ck & 1)*STG;
        #pragma unroll
        for (int i = 0; i < MT; i++) {
            int flat = tid + 256*i;
            int r = flat >> 3, u = flat & 7;
            uint32_t off = (uint32_t)(r*128 + ((u*16) ^ ((r & 7) << 4)));
            cpasync16(st + off, A + (size_t)(m0 + r)*K + ck*64 + u*8);
        }
        #pragma unroll
        for (int i = 0; i < 4; i++) {
            int flat = tid + 256*i;
            int r = flat >> 3, u = flat & 7;
            uint32_t off = (uint32_t)(r*128 + ((u*16) ^ ((r & 7) << 4)));
            cpasync16(st + ASZA + off, W + (size_t)(n0 + r)*K + ck*64 + u*8);
        }
    };

    prefetch(0);
    CP_COMMIT();

    for (int ck = 0; ck < nc; ck++) {
        if (ck + 1 < nc) { prefetch(ck + 1); CP_COMMIT(); CP_WAIT1(); }
        else             { CP_WAIT0(); }
        __syncthreads();

        uint32_t stb = sbase + (ck & 1)*STG;
        #pragma unroll
        for (int ks = 0; ks < 4; ks++) {
            int colx = (ks*32 + lcolB) ^ lxor;
            uint32_t a[MT][4];
            #pragma unroll
            for (int mi = 0; mi < MT; mi++) {
                uint32_t ad = stb + (wm*(MT*16) + mi*16 + lrow)*128 + colx;
                ldmx4(a[mi], ad);
            }
            uint32_t wv[4][2];
            #pragma unroll
            for (int p = 0; p < 2; p++) {
                uint32_t wd = stb + ASZA + (wn*32 + p*16 + lrow)*128 + colx;
                uint32_t r4[4];
                ldmx4(r4, wd);
                wv[2*p][0] = r4[0]; wv[2*p][1] = r4[2];
                wv[2*p+1][0] = r4[1]; wv[2*p+1][1] = r4[3];
            }
            #pragma unroll
            for (int mi = 0; mi < MT; mi++)
                #pragma unroll
                for (int nt = 0; nt < 4; nt++)
                    mma_f16(acc[mi][nt], a[mi], wv[nt][0], wv[nt][1]);
        }
        __syncthreads();
    }

    // ---- epilogue ----
    int r_l = lane >> 2, c_l = (lane & 3)*2;
    float2 bv[4], sv[4];
    #pragma unroll
    for (int nt = 0; nt < 4; nt++) {
        int col = n0 + wn*32 + nt*8 + c_l;
        bv[nt] = *(const float2*)(bias + col);
        if (MODE != 1) sv[nt] = *(const float2*)(S + col);
    }
    #pragma unroll
    for (int mi = 0; mi < MT; mi++) {
        int row0 = m0 + wm*(MT*16) + mi*16 + r_l;
        float mu0 = 0.f, rs0 = 0.f, mu1 = 0.f, rs1 = 0.f;
        if (MODE != 1) {
            float2 s0 = statsIn[(size_t)e*Nn + row0];
            float2 s1 = statsIn[(size_t)e*Nn + row0 + 8];
            mu0 = s0.x*invK; rs0 = rsqrtf(s0.y*invK - mu0*mu0 + 1e-5f);
            mu1 = s1.x*invK; rs1 = rsqrtf(s1.y*invK - mu1*mu1 + 1e-5f);
        }
        float ls0 = 0.f, lq0 = 0.f, ls1 = 0.f, lq1 = 0.f;
        #pragma unroll
        for (int nt = 0; nt < 4; nt++) {
            int col = n0 + wn*32 + nt*8 + c_l;
            float v0 = acc[mi][nt][0], v1 = acc[mi][nt][1];
            float v2 = acc[mi][nt][2], v3 = acc[mi][nt][3];
            if (MODE == 1) {
                v0 += bv[nt].x; v1 += bv[nt].y; v2 += bv[nt].x; v3 += bv[nt].y;
            } else {
                v0 = rs0*(v0 - mu0*sv[nt].x) + bv[nt].x;
                v1 = rs0*(v1 - mu0*sv[nt].y) + bv[nt].y;
                v2 = rs1*(v2 - mu1*sv[nt].x) + bv[nt].x;
                v3 = rs1*(v3 - mu1*sv[nt].y) + bv[nt].y;
            }
            size_t o0 = (size_t)row0*Ho + col;
            size_t o1 = (size_t)(row0+8)*Ho + col;
            if (MODE != 3) {
                v0 = v0 / (1.f + __expf(-v0));
                v1 = v1 / (1.f + __expf(-v1));
                v2 = v2 / (1.f + __expf(-v2));
                v3 = v3 / (1.f + __expf(-v3));
                __half2 h0 = __floats2half2_rn(v0, v1);
                __half2 h1 = __floats2half2_rn(v2, v3);
                *(uint32_t*)(Ch + o0) = *(uint32_t*)&h0;
                *(uint32_t*)(Ch + o1) = *(uint32_t*)&h1;
                ls0 += v0 + v1; lq0 += v0*v0 + v1*v1;
                ls1 += v2 + v3; lq1 += v2*v2 + v3*v3;
            } else {
                float2 x0 = *(float2*)(Cf + o0), x1 = *(float2*)(Cf + o1);
                float n00 = x0.x + scale*v0, n01 = x0.y + scale*v1;
                float n10 = x1.x + scale*v2, n11 = x1.y + scale*v3;
                *(float2*)(Cf + o0) = make_float2(n00, n01);
                *(float2*)(Cf + o1) = make_float2(n10, n11);
                __half2 h0 = __floats2half2_rn(n00, n01);
                __half2 h1 = __floats2half2_rn(n10, n11);
                *(uint32_t*)(Ch + o0) = *(uint32_t*)&h0;
                *(uint32_t*)(Ch + o1) = *(uint32_t*)&h1;
            }
        }
        if (MODE != 3) {
            ls0 += __shfl_xor_sync(0xffffffffu, ls0, 1); ls0 += __shfl_xor_sync(0xffffffffu, ls0, 2);
            lq0 += __shfl_xor_sync(0xffffffffu, lq0, 1); lq0 += __shfl_xor_sync(0xffffffffu, lq0, 2);
            ls1 += __shfl_xor_sync(0xffffffffu, ls1, 1); ls1 += __shfl_xor_sync(0xffffffffu, ls1, 2);
            lq1 += __shfl_xor_sync(0xffffffffu, lq1, 1); lq1 += __shfl_xor_sync(0xffffffffu, lq1, 2);
            if ((lane & 3) == 0) {
                float* p0 = (float*)&statsOut[(size_t)e*Nn + row0];
                atomicAdd(p0,     ls0);
                atomicAdd(p0 + 1, lq0);
                float* p1 = (float*)&statsOut[(size_t)e*Nn + row0 + 8];
                atomicAdd(p1,     ls1);
                atomicAdd(p1 + 1, lq1);
            }
        }
    }
}

// ---------------- combine: gather 2 expert rows per token; re-zero g_cnt ----------------
__global__ void combine_kernel(float* __restrict__ out) {
    if (blockIdx.x == 0 && threadIdx.x < Ee) g_cnt[threadIdx.x] = 0;
    size_t idx = (size_t)blockIdx.x*256 + threadIdx.x;
    if (idx >= (size_t)Nn*Dd/4) return;
    int n = (int)(idx / (Dd/4));
    int c4 = (int)(idx % (Dd/4));
    int4 a = g_asg[n];
    float2 w = g_wts[n];
    const float4* p1 = (const float4*)(g_xt + ((size_t)a.x*Nn + a.y)*Dd) + c4;
    const float4* p2 = (const float4*)(g_xt + ((size_t)a.z*Nn + a.w)*Dd) + c4;
    float4 v1 = *p1, v2 = *p2;
    float4 r;
    r.x = w.x*v1.x + w.y*v2.x;
    r.y = w.x*v1.y + w.y*v2.y;
    r.z = w.x*v1.z + w.y*v2.z;
    r.w = w.x*v1.w + w.y*v2.w;
    ((float4*)out)[idx] = r;
}

// ---------------- aux losses (independent of GEMM chain) ----------------
__global__ void aux_kernel(float* __restrict__ out, int out_size) {
    __shared__ float red[256];
    __shared__ float pe[Ee];
    int tid = threadIdx.x;
    float s = 0.f;
    for (int n = tid; n < Nn; n += 256) s += g_lse2[n];
    red[tid] = s; __syncthreads();
    #pragma unroll
    for (int o = 128; o; o >>= 1) { if (tid < o) red[tid] += red[tid+o]; __syncthreads(); }
    float z = red[0] / Nn;
    for (int e = 0; e < Ee; e++) {
        __syncthreads();
        float t = 0.f;
        for (int n = tid; n < Nn; n += 256) t += g_probs[n*Ee+e];
        red[tid] = t; __syncthreads();
        #pragma unroll
        for (int o = 128; o; o >>= 1) { if (tid < o) red[tid] += red[tid+o]; __syncthreads(); }
        if (tid == 0) pe[e] = red[0] / Nn;
    }
    __syncthreads();
    if (tid == 0) {
        float lb = 0.f;
        #pragma unroll
        for (int e = 0; e < Ee; e++) { float d = pe[e] - 1.0f/Ee; lb += d*d; }
        lb *= (float)Ee;
        float aux = 0.001f*z + 0.01f*lb;
        for (long long i = (long long)Nn*Dd; i < out_size; i++) out[i] = aux;
    }
}

// ---------------- side streams / events (host-side infra, created once) ----------------
static cudaStream_t s_prep = nullptr, s_prep2 = nullptr;
static cudaEvent_t s_evFork, s_evW1, s_evW2, s_evW3, s_evB, s_evR, s_evAux;
static void ensure_infra() {
    if (!s_prep) {
        cudaStreamCreateWithFlags(&s_prep,  cudaStreamNonBlocking);
        cudaStreamCreateWithFlags(&s_prep2, cudaStreamNonBlocking);
        cudaEventCreateWithFlags(&s_evFork, cudaEventDisableTiming);
        cudaEventCreateWithFlags(&s_evW1,   cudaEventDisableTiming);
        cudaEventCreateWithFlags(&s_evW2,   cudaEventDisableTiming);
        cudaEventCreateWithFlags(&s_evW3,   cudaEventDisableTiming);
        cudaEventCreateWithFlags(&s_evB,    cudaEventDisableTiming);
        cudaEventCreateWithFlags(&s_evR,    cudaEventDisableTiming);
        cudaEventCreateWithFlags(&s_evAux,  cudaEventDisableTiming);
    }
}

extern "C" void kernel_launch(void* const* d_in, const int* in_sizes, int n_in,
                              void* d_out, int out_size) {
    const float* x   = (const float*)d_in[0];
    const float* gw  = (const float*)d_in[1];
    const float* W1  = (const float*)d_in[2];
    const float* b1  = (const float*)d_in[3];
    const float* g1  = (const float*)d_in[4];
    const float* be1 = (const float*)d_in[5];
    const float* W2  = (const float*)d_in[6];
    const float* b2  = (const float*)d_in[7];
    const float* g2  = (const float*)d_in[8];
    const float* be2 = (const float*)d_in[9];
    const float* W3  = (const float*)d_in[10];
    const float* b3  = (const float*)d_in[11];
    float* out = (float*)d_out;

    float *xt, *beff, *s2p, *b2p, *s3p, *b3p;
    float2* stats;
    __half *xth, *h1, *h2, *w1, *w2, *w3;
    cudaGetSymbolAddress((void**)&xt,    g_xt);
    cudaGetSymbolAddress((void**)&xth,   g_xth);
    cudaGetSymbolAddress((void**)&h1,    g_h1);
    cudaGetSymbolAddress((void**)&h2,    g_h2);
    cudaGetSymbolAddress((void**)&beff,  g_beff);
    cudaGetSymbolAddress((void**)&w1,    g_w1);
    cudaGetSymbolAddress((void**)&w2,    g_w2);
    cudaGetSymbolAddress((void**)&w3,    g_w3);
    cudaGetSymbolAddress((void**)&s2p,   g_s2);
    cudaGetSymbolAddress((void**)&b2p,   g_b2p);
    cudaGetSymbolAddress((void**)&s3p,   g_s3);
    cudaGetSymbolAddress((void**)&b3p,   g_b3p);
    cudaGetSymbolAddress((void**)&stats, g_stats);

    ensure_infra();

    const int SMEM44 = 2*(4*32*128 + 16384);   // MT=4: 65536
    const int SMEM32 = 2*(2*32*128 + 16384);   // MT=2: 49152
    cudaFuncSetAttribute(gemm_hmma<1,4>, cudaFuncAttributeMaxDynamicSharedMemorySize, SMEM44);
    cudaFuncSetAttribute(gemm_hmma<2,4>, cudaFuncAttributeMaxDynamicSharedMemorySize, SMEM44);
    cudaFuncSetAttribute(gemm_hmma<3,2>, cudaFuncAttributeMaxDynamicSharedMemorySize, SMEM32);

    // ---- fork side streams ----
    cudaEventRecord(s_evFork, 0);
    cudaStreamWaitEvent(s_prep,  s_evFork, 0);
    cudaStreamWaitEvent(s_prep2, s_evFork, 0);

    // ---- side stream A: stats clear + W1 convert + LN folds ----
    zstats_kernel<<<(int)((8*(size_t)Ee*Nn + 255)/256), 256, 0, s_prep>>>();
    {
        long long t1 = (long long)Ee*Hh*Dd;
        wconv_kernel<<<(int)((t1+255)/256), 256, 0, s_prep>>>(W1, Dd+Tt, Dd, w1, t1);
    }
    cudaEventRecord(s_evW1, s_prep);
    wfold_kernel<<<(Ee*Hh + 7)/8, 256, 0, s_prep>>>(W2, g1, be1, b2, w2, s2p, b2p, Hh, Hh);
    cudaEventRecord(s_evW2, s_prep);
    wfold_kernel<<<(Ee*Dd + 7)/8, 256, 0, s_prep>>>(W3, g2, be2, b3, w3, s3p, b3p, Dd, Hh);
    cudaEventRecord(s_evW3, s_prep);

    // ---- side stream B: effective biases (warp-parallel) ----
    beff_kernel<<<(NSTEPS*Ee*Hh + 7)/8, 256, 0, s_prep2>>>(W1, b1);
    cudaEventRecord(s_evB, s_prep2);

    // ---- main stream: fused router+gather (g_cnt zeroed by previous combine) ----
    router_kernel<<<Nn, 256>>>(x, gw);
    cudaEventRecord(s_evR, 0);

    // ---- side stream B: aux loss runs concurrently with the GEMM chain ----
    cudaStreamWaitEvent(s_prep2, s_evR, 0);
    aux_kernel<<<1, 256, 0, s_prep2>>>(out, out_size);
    cudaEventRecord(s_evAux, s_prep2);

    // ---- main stream: flow-matching GEMM chain (mi slowest-varying grids) ----
    const float dt = 1.0f / NSTEPS;
    for (int s = 0; s < NSTEPS; s++) {
        float2* st1 = stats + (size_t)(2*s)  *Ee*Nn;
        float2* st2 = stats + (size_t)(2*s+1)*Ee*Nn;
        if (s == 0) { cudaStreamWaitEvent(0, s_evW1, 0); cudaStreamWaitEvent(0, s_evB, 0); }
        gemm_hmma<1,4><<<dim3(Hh/128, Ee, Nn/128), 256, SMEM44>>>(
            xth, w1, beff + s*Ee*Hh, nullptr, nullptr, st1, nullptr, h1, Dd, Hh, 1.f);
        if (s == 0) cudaStreamWaitEvent(0, s_evW2, 0);
        gemm_hmma<2,4><<<dim3(Hh/128, Ee, Nn/128), 256, SMEM44>>>(
            h1, w2, b2p, s2p, st1, st2, nullptr, h2, Hh, Hh, 1.f);
        if (s == 0) cudaStreamWaitEvent(0, s_evW3, 0);
        gemm_hmma<3,2><<<dim3(Dd/128, Ee, Nn/64), 256, SMEM32>>>(
            h2, w3, b3p, s3p, st2, nullptr, xt, xth, Hh, Dd, dt);
    }

    combine_kernel<<<(int)(((size_t)Nn*Dd/4 + 255)/256), 256>>>(out);
    cudaStreamWaitEvent(0, s_evAux, 0);   // join side stream before capture ends
}

// round 17
// speedup vs baseline: 1.1633x; 1.0660x over previous
#include <cuda_runtime.h>
#include <cuda_fp16.h>
#include <math.h>
#include <stdint.h>

#define Bb 4
#define Ss 512
#define Dd 512
#define Hh 1024
#define Tt 64
#define Ee 8
#define NSTEPS 4
#define Nn (Bb*Ss)   // 2048 tokens

// ---------------- scratch (static device memory; no allocation) ----------------
__device__ float  g_xt [(size_t)Ee*Nn*Dd];    // fp32 x_t, compact per expert (slot-major)
__device__ __half g_xth[(size_t)Ee*Nn*Dd];    // x_t fp16, compact
__device__ __half g_h1 [(size_t)Ee*Nn*Hh];
__device__ __half g_h2 [(size_t)Ee*Nn*Hh];
__device__ float g_probs[Nn*Ee];
__device__ float g_lse2[Nn];
__device__ float g_beff[NSTEPS*Ee*Hh];
__device__ __half g_w1[(size_t)Ee*Hh*Dd];
__device__ __half g_w2[(size_t)Ee*Hh*Hh];
__device__ __half g_w3[(size_t)Ee*Dd*Hh];
__device__ float g_s2 [Ee*Hh];
__device__ float g_b2p[Ee*Hh];
__device__ float g_s3 [Ee*Dd];
__device__ float g_b3p[Ee*Dd];
__device__ float2 g_stats[8*(size_t)Ee*Nn];
// routing (g_cnt starts zero via static init; combine re-zeros it each launch)
__device__ int    g_cnt[Ee];
__device__ int4   g_asg[Nn];
__device__ float2 g_wts[Nn];

__device__ __forceinline__ uint32_t smem_u32(const void* p) {
    uint32_t a;
    asm("{ .reg .u64 t; cvta.to.shared.u64 t, %1; cvt.u32.u64 %0, t; }" : "=r"(a) : "l"(p));
    return a;
}
__device__ __forceinline__ void ldmx4(uint32_t* r, uint32_t addr) {
    asm volatile("ldmatrix.sync.aligned.m8n8.x4.shared.b16 {%0,%1,%2,%3}, [%4];"
        : "=r"(r[0]), "=r"(r[1]), "=r"(r[2]), "=r"(r[3]) : "r"(addr));
}
__device__ __forceinline__ void mma_f16(float* d, const uint32_t* a, uint32_t b0, uint32_t b1) {
    asm volatile("mma.sync.aligned.m16n8k16.row.col.f32.f16.f16.f32 "
        "{%0,%1,%2,%3}, {%4,%5,%6,%7}, {%8,%9}, {%0,%1,%2,%3};"
        : "+f"(d[0]), "+f"(d[1]), "+f"(d[2]), "+f"(d[3])
        : "r"(a[0]), "r"(a[1]), "r"(a[2]), "r"(a[3]), "r"(b0), "r"(b1));
}
__device__ __forceinline__ void cpasync16(uint32_t dst, const void* src) {
    asm volatile("cp.async.cg.shared.global [%0], [%1], 16;" :: "r"(dst), "l"(src));
}
#define CP_COMMIT() asm volatile("cp.async.commit_group;" ::: "memory")
#define CP_WAIT1()  asm volatile("cp.async.wait_group 1;"  ::: "memory")
#define CP_WAIT0()  asm volatile("cp.async.wait_group 0;"  ::: "memory")

// ---------------- zero stats buffers ----------------
__global__ void zstats_kernel() {
    size_t idx = (size_t)blockIdx.x*256 + threadIdx.x;
    if (idx < 8*(size_t)Ee*Nn) g_stats[idx] = make_float2(0.f, 0.f);
}

// ---------------- router + fused gather ----------------
__global__ void router_kernel(const float* __restrict__ x, const float* __restrict__ gw) {
    int n = blockIdx.x;
    __shared__ float xs[Dd];
    __shared__ float lg[Ee];
    __shared__ int   sdst[2];
    int tid = threadIdx.x;
    for (int c = tid; c < Dd; c += 256) xs[c] = x[(size_t)n*Dd + c];
    __syncthreads();
    int w = tid >> 5, lane = tid & 31;
    float s = 0.f;
    const float* wrow = gw + (size_t)w*Dd;
    for (int c = lane; c < Dd; c += 32) s += xs[c]*wrow[c];
    #pragma unroll
    for (int o = 16; o; o >>= 1) s += __shfl_xor_sync(0xffffffffu, s, o);
    if (lane == 0) lg[w] = s;
    __syncthreads();
    if (tid == 0) {
        float m = lg[0];
        #pragma unroll
        for (int e = 1; e < Ee; e++) m = fmaxf(m, lg[e]);
        float ex[Ee], sum = 0.f;
        #pragma unroll
        for (int e = 0; e < Ee; e++) { ex[e] = expf(lg[e]-m); sum += ex[e]; }
        float lse = m + logf(sum);
        g_lse2[n] = lse*lse;
        float p[Ee];
        #pragma unroll
        for (int e = 0; e < Ee; e++) { p[e] = ex[e]/sum; g_probs[n*Ee+e] = p[e]; }
        int i1 = 0;
        #pragma unroll
        for (int e = 1; e < Ee; e++) if (p[e] > p[i1]) i1 = e;
        int i2 = (i1 == 0) ? 1 : 0;
        #pragma unroll
        for (int e = 0; e < Ee; e++) { if (e == i1) continue; if (p[e] > p[i2]) i2 = e; }
        float denom = p[i1] + p[i2] + 1e-9f;
        int s1 = atomicAdd(&g_cnt[i1], 1);
        int s2 = atomicAdd(&g_cnt[i2], 1);
        g_asg[n] = make_int4(i1, s1, i2, s2);
        g_wts[n] = make_float2(p[i1]/denom, p[i2]/denom);
        sdst[0] = i1*Nn + s1;
        sdst[1] = i2*Nn + s2;
    }
    __syncthreads();
    #pragma unroll
    for (int cpy = 0; cpy < 2; cpy++) {
        size_t base = (size_t)sdst[cpy]*Dd;
        for (int c4 = tid; c4 < Dd/4; c4 += 256) {
            float4 v = *(const float4*)&xs[c4*4];
            *(float4*)(g_xt + base + c4*4) = v;
            __half2 h0 = __floats2half2_rn(v.x, v.y);
            __half2 h1 = __floats2half2_rn(v.z, v.w);
            *(uint32_t*)(g_xth + base + c4*4)     = *(uint32_t*)&h0;
            *(uint32_t*)(g_xth + base + c4*4 + 2) = *(uint32_t*)&h1;
        }
    }
}

// ---------------- all steps' effective bias: one warp per row ----------------
__global__ void beff_kernel(const float* __restrict__ W1, const float* __restrict__ b1) {
    int row = blockIdx.x*8 + (threadIdx.x >> 5);
    int lane = threadIdx.x & 31;
    if (row >= NSTEPS*Ee*Hh) return;
    int st = row / (Ee*Hh);
    int r  = row % (Ee*Hh);
    float t = st * (1.0f / NSTEPS);
    const float* wrow = W1 + (size_t)r*(Dd+Tt) + Dd;
    const float c0 = -9.210340371976184f / 31.0f;
    float f = __expf(c0 * (float)lane);
    float a = t * f;
    float sn, cs;
    __sincosf(a, &sn, &cs);
    float s = sn*wrow[lane] + cs*wrow[32+lane];
    #pragma unroll
    for (int o = 16; o; o >>= 1) s += __shfl_xor_sync(0xffffffffu, s, o);
    if (lane == 0) g_beff[row] = b1[r] + s;
}

// ---------------- W1 convert: fp32 (strided) -> fp16 ----------------
__global__ void wconv_kernel(const float* __restrict__ src, int ld, int cols,
                             __half* __restrict__ dst, long long total) {
    long long idx = (long long)blockIdx.x*256 + threadIdx.x;
    if (idx >= total) return;
    long long r = idx / cols, c = idx % cols;
    dst[idx] = __float2half_rn(src[r*ld + c]);
}

// ---------------- fold LN affine into weights ----------------
__global__ void wfold_kernel(const float* __restrict__ W, const float* __restrict__ g,
                             const float* __restrict__ be, const float* __restrict__ b,
                             __half* __restrict__ wo, float* __restrict__ So,
                             float* __restrict__ bo, int Ho, int Kc) {
    int row = blockIdx.x*8 + (threadIdx.x >> 5);
    int lane = threadIdx.x & 31;
    if (row >= Ee*Ho) return;
    int e = row / Ho;
    const float* wr = W + (size_t)row*Kc;
    const float* gr = g + (size_t)e*Kc;
    const float* ber = be + (size_t)e*Kc;
    __half* wor = wo + (size_t)row*Kc;
    float s = 0.f, bb = 0.f;
    for (int k = lane; k < Kc; k += 32) {
        float wv = wr[k];
        __half h = __float2half_rn(wv * gr[k]);
        wor[k] = h;
        s  += __half2float(h);
        bb += wv * ber[k];
    }
    #pragma unroll
    for (int o = 16; o; o >>= 1) {
        s  += __shfl_xor_sync(0xffffffffu, s, o);
        bb += __shfl_xor_sync(0xffffffffu, bb, o);
    }
    if (lane == 0) { So[row] = s; bo[row] = b[row] + bb; }
}

// ================= HMMA batched NT GEMM (compile-time K/Ho, 2-stage cp.async) =================
// Grid: (ntiles, Ee, mtiles) — mi slowest-varying: active tiles front-packed.
// MODE 1: y = acc + bias; SiLU; emit fp16; stats-out.
// MODE 2: y = rstd*(acc - mu*S) + bias; SiLU; emit fp16; stats-out.
// MODE 3: y = rstd*(acc - mu*S) + bias; xt += scale*y; emit fp32 + fp16.
template<int MODE, int MT, int K, int Ho>
__global__ __launch_bounds__(256, 2)
void gemm_hmma(const __half* __restrict__ A, const __half* __restrict__ W,
               const float* __restrict__ bias, const float* __restrict__ S,
               const float2* __restrict__ statsIn, float2* __restrict__ statsOut,
               float* __restrict__ Cf, __half* __restrict__ Ch,
               float scale) {
    constexpr int BM   = 32*MT;
    constexpr int ASZA = BM*128;
    constexpr int STG  = ASZA + 16384;
    constexpr int nc   = K >> 6;
    int e = blockIdx.y;
    const int m0 = blockIdx.z*BM, n0 = blockIdx.x*128;
    if (m0 >= g_cnt[e]) return;
    extern __shared__ __align__(128) char smem[];
    const uint32_t sbase = smem_u32(smem);
    int tid = threadIdx.x, wid = tid >> 5, lane = tid & 31;
    int wm = wid & 1, wn = wid >> 1;
    A    += (size_t)e*Nn*K;
    W    += (size_t)e*Ho*K;
    bias += (size_t)e*Ho;
    if (MODE != 1) S += (size_t)e*Ho;
    if (MODE == 3) Cf += (size_t)e*Nn*Ho;
    Ch   += (size_t)e*Nn*Ho;
    constexpr float invK = 1.f / (float)K;

    int part = lane >> 3, rip = lane & 7;
    int lrow  = (part & 1)*8 + rip;
    int lcolB = (part >> 1)*16;
    int lxor  = (lrow & 7) << 4;

    float acc[MT][4][4];
    #pragma unroll
    for (int i = 0; i < MT; i++)
        #pragma unroll
        for (int j = 0; j < 4; j++)
            #pragma unroll
            for (int q = 0; q < 4; q++) acc[i][j][q] = 0.f;

    auto prefetch = [&](int ck) {
        uint32_t st = sbase + (ck & 1)*STG;
        #pragma unroll
        for (int i = 0; i < MT; i++) {
            int flat = tid + 256*i;
            int r = flat >> 3, u = flat & 7;
            uint32_t off = (uint32_t)(r*128 + ((u*16) ^ ((r & 7) << 4)));
            cpasync16(st + off, A + (size_t)(m0 + r)*K + ck*64 + u*8);
        }
        #pragma unroll
        for (int i = 0; i < 4; i++) {
            int flat = tid + 256*i;
            int r = flat >> 3, u = flat & 7;
            uint32_t off = (uint32_t)(r*128 + ((u*16) ^ ((r & 7) << 4)));
            cpasync16(st + ASZA + off, W + (size_t)(n0 + r)*K + ck*64 + u*8);
        }
    };

    prefetch(0);
    CP_COMMIT();

    #pragma unroll
    for (int ck = 0; ck < nc; ck++) {
        if (ck + 1 < nc) { prefetch(ck + 1); CP_COMMIT(); CP_WAIT1(); }
        else             { CP_WAIT0(); }
        __syncthreads();

        uint32_t stb = sbase + (ck & 1)*STG;
        #pragma unroll
        for (int ks = 0; ks < 4; ks++) {
            int colx = (ks*32 + lcolB) ^ lxor;
            uint32_t a[MT][4];
            #pragma unroll
            for (int mi = 0; mi < MT; mi++) {
                uint32_t ad = stb + (wm*(MT*16) + mi*16 + lrow)*128 + colx;
                ldmx4(a[mi], ad);
            }
            uint32_t wv[4][2];
            #pragma unroll
            for (int p = 0; p < 2; p++) {
                uint32_t wd = stb + ASZA + (wn*32 + p*16 + lrow)*128 + colx;
                uint32_t r4[4];
                ldmx4(r4, wd);
                wv[2*p][0] = r4[0]; wv[2*p][1] = r4[2];
                wv[2*p+1][0] = r4[1]; wv[2*p+1][1] = r4[3];
            }
            #pragma unroll
            for (int mi = 0; mi < MT; mi++)
                #pragma unroll
                for (int nt = 0; nt < 4; nt++)
                    mma_f16(acc[mi][nt], a[mi], wv[nt][0], wv[nt][1]);
        }
        __syncthreads();
    }

    // ---- epilogue ----
    int r_l = lane >> 2, c_l = (lane & 3)*2;
    float2 bv[4], sv[4];
    #pragma unroll
    for (int nt = 0; nt < 4; nt++) {
        int col = n0 + wn*32 + nt*8 + c_l;
        bv[nt] = *(const float2*)(bias + col);
        if (MODE != 1) sv[nt] = *(const float2*)(S + col);
    }
    #pragma unroll
    for (int mi = 0; mi < MT; mi++) {
        int row0 = m0 + wm*(MT*16) + mi*16 + r_l;
        float mu0 = 0.f, rs0 = 0.f, mu1 = 0.f, rs1 = 0.f;
        if (MODE != 1) {
            float2 s0 = statsIn[(size_t)e*Nn + row0];
            float2 s1 = statsIn[(size_t)e*Nn + row0 + 8];
            mu0 = s0.x*invK; rs0 = rsqrtf(s0.y*invK - mu0*mu0 + 1e-5f);
            mu1 = s1.x*invK; rs1 = rsqrtf(s1.y*invK - mu1*mu1 + 1e-5f);
        }
        float ls0 = 0.f, lq0 = 0.f, ls1 = 0.f, lq1 = 0.f;
        #pragma unroll
        for (int nt = 0; nt < 4; nt++) {
            int col = n0 + wn*32 + nt*8 + c_l;
            float v0 = acc[mi][nt][0], v1 = acc[mi][nt][1];
            float v2 = acc[mi][nt][2], v3 = acc[mi][nt][3];
            if (MODE == 1) {
                v0 += bv[nt].x; v1 += bv[nt].y; v2 += bv[nt].x; v3 += bv[nt].y;
            } else {
                v0 = rs0*(v0 - mu0*sv[nt].x) + bv[nt].x;
                v1 = rs0*(v1 - mu0*sv[nt].y) + bv[nt].y;
                v2 = rs1*(v2 - mu1*sv[nt].x) + bv[nt].x;
                v3 = rs1*(v3 - mu1*sv[nt].y) + bv[nt].y;
            }
            size_t o0 = (size_t)row0*Ho + col;
            size_t o1 = (size_t)(row0+8)*Ho + col;
            if (MODE != 3) {
                v0 = v0 / (1.f + __expf(-v0));
                v1 = v1 / (1.f + __expf(-v1));
                v2 = v2 / (1.f + __expf(-v2));
                v3 = v3 / (1.f + __expf(-v3));
                __half2 h0 = __floats2half2_rn(v0, v1);
                __half2 h1 = __floats2half2_rn(v2, v3);
                *(uint32_t*)(Ch + o0) = *(uint32_t*)&h0;
                *(uint32_t*)(Ch + o1) = *(uint32_t*)&h1;
                ls0 += v0 + v1; lq0 += v0*v0 + v1*v1;
                ls1 += v2 + v3; lq1 += v2*v2 + v3*v3;
            } else {
                float2 x0 = *(float2*)(Cf + o0), x1 = *(float2*)(Cf + o1);
                float n00 = x0.x + scale*v0, n01 = x0.y + scale*v1;
                float n10 = x1.x + scale*v2, n11 = x1.y + scale*v3;
                *(float2*)(Cf + o0) = make_float2(n00, n01);
                *(float2*)(Cf + o1) = make_float2(n10, n11);
                __half2 h0 = __floats2half2_rn(n00, n01);
                __half2 h1 = __floats2half2_rn(n10, n11);
                *(uint32_t*)(Ch + o0) = *(uint32_t*)&h0;
                *(uint32_t*)(Ch + o1) = *(uint32_t*)&h1;
            }
        }
        if (MODE != 3) {
            ls0 += __shfl_xor_sync(0xffffffffu, ls0, 1); ls0 += __shfl_xor_sync(0xffffffffu, ls0, 2);
            lq0 += __shfl_xor_sync(0xffffffffu, lq0, 1); lq0 += __shfl_xor_sync(0xffffffffu, lq0, 2);
            ls1 += __shfl_xor_sync(0xffffffffu, ls1, 1); ls1 += __shfl_xor_sync(0xffffffffu, ls1, 2);
            lq1 += __shfl_xor_sync(0xffffffffu, lq1, 1); lq1 += __shfl_xor_sync(0xffffffffu, lq1, 2);
            if ((lane & 3) == 0) {
                float* p0 = (float*)&statsOut[(size_t)e*Nn + row0];
                atomicAdd(p0,     ls0);
                atomicAdd(p0 + 1, lq0);
                float* p1 = (float*)&statsOut[(size_t)e*Nn + row0 + 8];
                atomicAdd(p1,     ls1);
                atomicAdd(p1 + 1, lq1);
            }
        }
    }
}

// ---------------- combine: gather 2 expert rows per token; re-zero g_cnt ----------------
__global__ void combine_kernel(float* __restrict__ out) {
    if (blockIdx.x == 0 && threadIdx.x < Ee) g_cnt[threadIdx.x] = 0;
    size_t idx = (size_t)blockIdx.x*256 + threadIdx.x;
    if (idx >= (size_t)Nn*Dd/4) return;
    int n = (int)(idx / (Dd/4));
    int c4 = (int)(idx % (Dd/4));
    int4 a = g_asg[n];
    float2 w = g_wts[n];
    const float4* p1 = (const float4*)(g_xt + ((size_t)a.x*Nn + a.y)*Dd) + c4;
    const float4* p2 = (const float4*)(g_xt + ((size_t)a.z*Nn + a.w)*Dd) + c4;
    float4 v1 = *p1, v2 = *p2;
    float4 r;
    r.x = w.x*v1.x + w.y*v2.x;
    r.y = w.x*v1.y + w.y*v2.y;
    r.z = w.x*v1.z + w.y*v2.z;
    r.w = w.x*v1.w + w.y*v2.w;
    ((float4*)out)[idx] = r;
}

// ---------------- aux losses (independent of GEMM chain) ----------------
__global__ void aux_kernel(float* __restrict__ out, int out_size) {
    __shared__ float red[256];
    __shared__ float pe[Ee];
    int tid = threadIdx.x;
    float s = 0.f;
    for (int n = tid; n < Nn; n += 256) s += g_lse2[n];
    red[tid] = s; __syncthreads();
    #pragma unroll
    for (int o = 128; o; o >>= 1) { if (tid < o) red[tid] += red[tid+o]; __syncthreads(); }
    float z = red[0] / Nn;
    for (int e = 0; e < Ee; e++) {
        __syncthreads();
        float t = 0.f;
        for (int n = tid; n < Nn; n += 256) t += g_probs[n*Ee+e];
        red[tid] = t; __syncthreads();
        #pragma unroll
        for (int o = 128; o; o >>= 1) { if (tid < o) red[tid] += red[tid+o]; __syncthreads(); }
        if (tid == 0) pe[e] = red[0] / Nn;
    }
    __syncthreads();
    if (tid == 0) {
        float lb = 0.f;
        #pragma unroll
        for (int e = 0; e < Ee; e++) { float d = pe[e] - 1.0f/Ee; lb += d*d; }
        lb *= (float)Ee;
        float aux = 0.001f*z + 0.01f*lb;
        for (long long i = (long long)Nn*Dd; i < out_size; i++) out[i] = aux;
    }
}

// ---------------- side streams / events (host-side infra, created once) ----------------
static cudaStream_t s_prep = nullptr, s_prep2 = nullptr;
static cudaEvent_t s_evFork, s_evW1, s_evW2, s_evW3, s_evB, s_evR, s_evAux;
static void ensure_infra() {
    if (!s_prep) {
        cudaStreamCreateWithFlags(&s_prep,  cudaStreamNonBlocking);
        cudaStreamCreateWithFlags(&s_prep2, cudaStreamNonBlocking);
        cudaEventCreateWithFlags(&s_evFork, cudaEventDisableTiming);
        cudaEventCreateWithFlags(&s_evW1,   cudaEventDisableTiming);
        cudaEventCreateWithFlags(&s_evW2,   cudaEventDisableTiming);
        cudaEventCreateWithFlags(&s_evW3,   cudaEventDisableTiming);
        cudaEventCreateWithFlags(&s_evB,    cudaEventDisableTiming);
        cudaEventCreateWithFlags(&s_evR,    cudaEventDisableTiming);
        cudaEventCreateWithFlags(&s_evAux,  cudaEventDisableTiming);
    }
}

extern "C" void kernel_launch(void* const* d_in, const int* in_sizes, int n_in,
                              void* d_out, int out_size) {
    const float* x   = (const float*)d_in[0];
    const float* gw  = (const float*)d_in[1];
    const float* W1  = (const float*)d_in[2];
    const float* b1  = (const float*)d_in[3];
    const float* g1  = (const float*)d_in[4];
    const float* be1 = (const float*)d_in[5];
    const float* W2  = (const float*)d_in[6];
    const float* b2  = (const float*)d_in[7];
    const float* g2  = (const float*)d_in[8];
    const float* be2 = (const float*)d_in[9];
    const float* W3  = (const float*)d_in[10];
    const float* b3  = (const float*)d_in[11];
    float* out = (float*)d_out;

    float *xt, *beff, *s2p, *b2p, *s3p, *b3p;
    float2* stats;
    __half *xth, *h1, *h2, *w1, *w2, *w3;
    cudaGetSymbolAddress((void**)&xt,    g_xt);
    cudaGetSymbolAddress((void**)&xth,   g_xth);
    cudaGetSymbolAddress((void**)&h1,    g_h1);
    cudaGetSymbolAddress((void**)&h2,    g_h2);
    cudaGetSymbolAddress((void**)&beff,  g_beff);
    cudaGetSymbolAddress((void**)&w1,    g_w1);
    cudaGetSymbolAddress((void**)&w2,    g_w2);
    cudaGetSymbolAddress((void**)&w3,    g_w3);
    cudaGetSymbolAddress((void**)&s2p,   g_s2);
    cudaGetSymbolAddress((void**)&b2p,   g_b2p);
    cudaGetSymbolAddress((void**)&s3p,   g_s3);
    cudaGetSymbolAddress((void**)&b3p,   g_b3p);
    cudaGetSymbolAddress((void**)&stats, g_stats);

    ensure_infra();

    const int SMEM44 = 2*(4*32*128 + 16384);   // MT=4: 65536
    const int SMEM32 = 2*(2*32*128 + 16384);   // MT=2: 49152
    cudaFuncSetAttribute((gemm_hmma<1,4,Dd,Hh>), cudaFuncAttributeMaxDynamicSharedMemorySize, SMEM44);
    cudaFuncSetAttribute((gemm_hmma<2,4,Hh,Hh>), cudaFuncAttributeMaxDynamicSharedMemorySize, SMEM44);
    cudaFuncSetAttribute((gemm_hmma<3,2,Hh,Dd>), cudaFuncAttributeMaxDynamicSharedMemorySize, SMEM32);

    // ---- fork side streams ----
    cudaEventRecord(s_evFork, 0);
    cudaStreamWaitEvent(s_prep,  s_evFork, 0);
    cudaStreamWaitEvent(s_prep2, s_evFork, 0);

    // ---- side stream A: W1 convert + LN folds (wconv first so evW1 fires ASAP) ----
    {
        long long t1 = (long long)Ee*Hh*Dd;
        wconv_kernel<<<(int)((t1+255)/256), 256, 0, s_prep>>>(W1, Dd+Tt, Dd, w1, t1);
    }
    cudaEventRecord(s_evW1, s_prep);
    wfold_kernel<<<(Ee*Hh + 7)/8, 256, 0, s_prep>>>(W2, g1, be1, b2, w2, s2p, b2p, Hh, Hh);
    cudaEventRecord(s_evW2, s_prep);
    wfold_kernel<<<(Ee*Dd + 7)/8, 256, 0, s_prep>>>(W3, g2, be2, b3, w3, s3p, b3p, Dd, Hh);
    cudaEventRecord(s_evW3, s_prep);

    // ---- side stream B: effective biases + stats clear (both short) ----
    beff_kernel<<<(NSTEPS*Ee*Hh + 7)/8, 256, 0, s_prep2>>>(W1, b1);
    zstats_kernel<<<(int)((8*(size_t)Ee*Nn + 255)/256), 256, 0, s_prep2>>>();
    cudaEventRecord(s_evB, s_prep2);

    // ---- main stream: fused router+gather (g_cnt zeroed by previous combine) ----
    router_kernel<<<Nn, 256>>>(x, gw);
    cudaEventRecord(s_evR, 0);

    // ---- side stream B: aux loss runs concurrently with the GEMM chain ----
    cudaStreamWaitEvent(s_prep2, s_evR, 0);
    aux_kernel<<<1, 256, 0, s_prep2>>>(out, out_size);
    cudaEventRecord(s_evAux, s_prep2);

    // ---- main stream: flow-matching GEMM chain (compile-time K/Ho) ----
    const float dt = 1.0f / NSTEPS;
    for (int s = 0; s < NSTEPS; s++) {
        float2* st1 = stats + (size_t)(2*s)  *Ee*Nn;
        float2* st2 = stats + (size_t)(2*s+1)*Ee*Nn;
        if (s == 0) { cudaStreamWaitEvent(0, s_evW1, 0); cudaStreamWaitEvent(0, s_evB, 0); }
        gemm_hmma<1,4,Dd,Hh><<<dim3(Hh/128, Ee, Nn/128), 256, SMEM44>>>(
            xth, w1, beff + s*Ee*Hh, nullptr, nullptr, st1, nullptr, h1, 1.f);
        if (s == 0) cudaStreamWaitEvent(0, s_evW2, 0);
        gemm_hmma<2,4,Hh,Hh><<<dim3(Hh/128, Ee, Nn/128), 256, SMEM44>>>(
            h1, w2, b2p, s2p, st1, st2, nullptr, h2, 1.f);
        if (s == 0) cudaStreamWaitEvent(0, s_evW3, 0);
        gemm_hmma<3,2,Hh,Dd><<<dim3(Dd/128, Ee, Nn/64), 256, SMEM32>>>(
            h2, w3, b3p, s3p, st2, nullptr, xt, xth, dt);
    }

    combine_kernel<<<(int)(((size_t)Nn*Dd/4 + 255)/256), 256>>>(out);
    cudaStreamWaitEvent(0, s_evAux, 0);   // join side stream before capture ends
}